// round 4
// baseline (speedup 1.0000x reference)
#include <cuda_runtime.h>
#include <math.h>

// GGNN + Set2Set fully fused, one CTA per graph. R4: f32x2 packed FMA matmuls,
// pre-baked transposed+swizzled weight tiles, register-accumulated etype sum.

#define NPG   200
#define EPG   3200
#define NET   6
#define NTH   640

// SMEM float offsets (pitch 64, rotation-swizzled)
#define H_OFF   0
#define A_OFF   12800
#define S_OFF   25600          // also GRU temp t1
#define T2_OFF  38400
#define W_OFF   51200          // 64x64 weight tile (pre-swizzled image)
#define ESRC_BYTE (55296*4)
#define OFF_BYTE  (ESRC_BYTE + 3200)
#define SMEM_BYTES (OFF_BYTE + 1216*2)   // 226816

// logical float4-column c4 of row stored at physical slot ((c4+row)&15)
#define SWZ4(row, c4) (((row)<<6) + ((((c4)+(row))&15)<<2))

// 12 pre-baked 64x64 weight tiles in final swizzled layout:
// tiles 0..5  = W_edge[t] transposed  (wT[o][d] = W_edge[t][d][o])
// tiles 6..11 = GRU pass p slice      (wT[c][d] = M_p[g0_p + c][d])
__device__ float g_wt[12 * 4096];

__device__ __forceinline__ float sigf(float x) { return 1.0f / (1.0f + __expf(-x)); }
__device__ __forceinline__ float tanhfast(float x) {
    x = fminf(fmaxf(x, -15.0f), 15.0f);
    float e = __expf(2.0f * x);
    return (e - 1.0f) / (e + 1.0f);
}

__device__ __forceinline__ void ffma2(unsigned long long& d,
                                      unsigned long long a, unsigned long long b) {
    asm("fma.rn.f32x2 %0, %1, %2, %0;" : "+l"(d) : "l"(a), "l"(b));
}
__device__ __forceinline__ void fadd2(unsigned long long& d, unsigned long long a) {
    asm("add.rn.f32x2 %0, %1, %0;" : "+l"(d) : "l"(a));
}
__device__ __forceinline__ float redp(unsigned long long v) {
    float lo, hi;
    asm("mov.b64 {%0, %1}, %2;" : "=f"(lo), "=f"(hi) : "l"(v));
    return lo + hi;
}
__device__ __forceinline__ unsigned long long pack2(float x, float y) {
    unsigned long long r;
    asm("mov.b64 %0, {%1, %2};" : "=l"(r) : "f"(x), "f"(y));
    return r;
}

// acc2[r*4+j] accumulates (even-k partial, odd-k partial) for output
// (row r0+r, col tx*4+j) of src[200x64] @ wT^T. Both operands swizzled.
__device__ __forceinline__ void mm5p(const float* __restrict__ src,
                                     const float* __restrict__ wT,
                                     int r0, int tx, unsigned long long* acc2) {
#pragma unroll 4
    for (int db = 0; db < 16; db++) {
        ulonglong2 wv0 = *(const ulonglong2*)(wT + SWZ4(tx * 4 + 0, db));
        ulonglong2 wv1 = *(const ulonglong2*)(wT + SWZ4(tx * 4 + 1, db));
        ulonglong2 wv2 = *(const ulonglong2*)(wT + SWZ4(tx * 4 + 2, db));
        ulonglong2 wv3 = *(const ulonglong2*)(wT + SWZ4(tx * 4 + 3, db));
#pragma unroll
        for (int r = 0; r < 5; r++) {
            ulonglong2 sv = *(const ulonglong2*)(src + SWZ4(r0 + r, db));
            ffma2(acc2[r*4+0], sv.x, wv0.x);
            ffma2(acc2[r*4+0], sv.y, wv0.y);
            ffma2(acc2[r*4+1], sv.x, wv1.x);
            ffma2(acc2[r*4+1], sv.y, wv1.y);
            ffma2(acc2[r*4+2], sv.x, wv2.x);
            ffma2(acc2[r*4+2], sv.y, wv2.y);
            ffma2(acc2[r*4+3], sv.x, wv3.x);
            ffma2(acc2[r*4+3], sv.y, wv3.y);
        }
    }
}

__global__ void prep_kernel(const float* __restrict__ W_edge,
                            const float* __restrict__ gWih,
                            const float* __restrict__ gWhh) {
    int i = blockIdx.x * blockDim.x + threadIdx.x;
    if (i >= 12 * 4096) return;
    int tile = i >> 12, r = i & 4095;
    int row = r >> 6, d = r & 63;
    float v;
    if (tile < 6) {
        v = W_edge[(tile * 64 + d) * 64 + row];            // transpose
    } else {
        int p = tile - 6;
        const int g0s[6] = { 0, 0, 128, 128, 64, 64 };
        const float* M = (p == 0 || p == 3 || p == 4) ? gWih : gWhh;
        v = M[(g0s[p] + row) * 64 + d];                    // no transpose
    }
    g_wt[tile * 4096 + (row << 6) + ((((d >> 2) + row) & 15) << 2) + (d & 3)] = v;
}

__global__ __launch_bounds__(NTH, 1)
void ggnn_fused_kernel(
    const float* __restrict__ feats,
    const float* __restrict__ b_edge,
    const float* __restrict__ gbih,
    const float* __restrict__ gbhh,
    const float* __restrict__ wih0, const float* __restrict__ whh0,
    const float* __restrict__ bih0, const float* __restrict__ bhh0,
    const float* __restrict__ wih1, const float* __restrict__ whh1,
    const float* __restrict__ bih1, const float* __restrict__ bhh1,
    const float* __restrict__ wih2, const float* __restrict__ whh2,
    const float* __restrict__ bih2, const float* __restrict__ bhh2,
    const float* __restrict__ Wp,
    const float* __restrict__ bp,
    const int* __restrict__ g_src,
    const int* __restrict__ g_dst,
    const int* __restrict__ g_ety,
    float* __restrict__ out)
{
    extern __shared__ float smem[];
    float* h_sm  = smem + H_OFF;
    float* a_sm  = smem + A_OFF;
    float* s_sm  = smem + S_OFF;   // also t1
    float* t2_sm = smem + T2_OFF;
    float* w_sm  = smem + W_OFF;
    unsigned char*  esrc = (unsigned char*)smem + ESRC_BYTE;
    unsigned short* off  = (unsigned short*)((char*)smem + OFF_BYTE);

    const int tid = threadIdx.x;
    const int g = blockIdx.x;
    const int nbase = g * NPG;
    const int ebase = g * EPG;
    const int tx = tid & 15;
    const int rt = tid >> 4;      // 0..39
    const int r0 = rt * 5;
    const bool has2 = (tid < 384);  // staging: 1024 float4 over 640 threads

    // ---------- load feats (swizzled) + counting sort by (etype, dst) ----------
    {
        int* cnt  = (int*)w_sm;
        int* csum = cnt + 1280;
        for (int i = tid; i < 1280; i += NTH) cnt[i] = 0;
        for (int i = tid; i < NPG * 64; i += NTH) {
            int n = i >> 6, d = i & 63;
            h_sm[SWZ4(n, d >> 2) + (d & 3)] = feats[(nbase + n) * 64 + d];
        }
        __syncthreads();
        for (int e = tid; e < EPG; e += NTH) {
            int key = g_ety[ebase + e] * NPG + (g_dst[ebase + e] - nbase);
            atomicAdd(&cnt[key], 1);
        }
        __syncthreads();
        if (tid < 256) {
            int s = 0;
#pragma unroll
            for (int j = 0; j < 5; j++) s += cnt[tid * 5 + j];
            csum[tid] = s;
        }
        __syncthreads();
        if (tid < 32) {
            int s = 0;
#pragma unroll
            for (int j = 0; j < 8; j++) s += csum[tid * 8 + j];
            int v = s;
            for (int o = 1; o < 32; o <<= 1) {
                int u = __shfl_up_sync(0xffffffffu, v, o);
                if (tid >= o) v += u;
            }
            int run = v - s;
#pragma unroll
            for (int j = 0; j < 8; j++) {
                int c = csum[tid * 8 + j];
                csum[tid * 8 + j] = run;
                run += c;
            }
        }
        __syncthreads();
        if (tid < 256) {
            int run = csum[tid];
#pragma unroll
            for (int j = 0; j < 5; j++) {
                int idx = tid * 5 + j;
                int c = cnt[idx];
                if (idx < 1216) off[idx] = (unsigned short)run;
                run += c;
            }
        }
        __syncthreads();
        for (int i = tid; i < 1200; i += NTH) cnt[i] = off[i];
        __syncthreads();
        for (int e = tid; e < EPG; e += NTH) {
            int key = g_ety[ebase + e] * NPG + (g_dst[ebase + e] - nbase);
            int pos = atomicAdd(&cnt[key], 1);
            esrc[pos] = (unsigned char)(g_src[ebase + e] - nbase);
        }
    }

    // ---------- GatedGraphConv: 5 steps ----------
    for (int step = 0; step < 5; step++) {
        // a accumulated in registers across all 6 etypes
        unsigned long long aacc[20];
#pragma unroll
        for (int i = 0; i < 20; i++) aacc[i] = 0ull;

        for (int t = 0; t < NET; t++) {
            // prefetch weight tile image (before barrier — hides L2 latency)
            const float4* wt4 = (const float4*)g_wt + t * 1024;
            float4 wa = wt4[tid];
            float4 wb;
            if (has2) wb = wt4[640 + tid];
            __syncthreads();   // previous mm done reading w_sm / s_sm
            ((float4*)w_sm)[tid] = wa;
            if (has2) ((float4*)w_sm)[640 + tid] = wb;
            // aggregate s[n][:] over etype-t edges
            {
                int dg = tid & 15, ns = tid >> 4;
                for (int n = ns; n < NPG; n += 40) {
                    int b = t * NPG + n;
                    int j0 = off[b], j1 = off[b + 1];
                    ulonglong2 acc4; acc4.x = 0ull; acc4.y = 0ull;
                    for (int j = j0; j < j1; j++) {
                        ulonglong2 v = *(const ulonglong2*)(h_sm + SWZ4((int)esrc[j], dg));
                        fadd2(acc4.x, v.x);
                        fadd2(acc4.y, v.y);
                    }
                    *(ulonglong2*)(s_sm + SWZ4(n, dg)) = acc4;
                }
            }
            __syncthreads();
            mm5p(s_sm, w_sm, r0, tx, aacc);
            // bias: aacc[r][j] += cnt(r) * b_edge[t][col j]   (into even half)
            float4 be = *(const float4*)(b_edge + t * 64 + tx * 4);
            unsigned long long be2x = pack2(be.x, 0.0f);
            unsigned long long be2y = pack2(be.y, 0.0f);
            unsigned long long be2z = pack2(be.z, 0.0f);
            unsigned long long be2w = pack2(be.w, 0.0f);
#pragma unroll
            for (int r = 0; r < 5; r++) {
                int row = r0 + r;
                float cf = (float)(off[t * NPG + row + 1] - off[t * NPG + row]);
                unsigned long long cf2 = pack2(cf, 0.0f);
                ffma2(aacc[r*4+0], cf2, be2x);
                ffma2(aacc[r*4+1], cf2, be2y);
                ffma2(aacc[r*4+2], cf2, be2z);
                ffma2(aacc[r*4+3], cf2, be2w);
            }
        }
        // materialize a
#pragma unroll
        for (int r = 0; r < 5; r++) {
            float4 v = make_float4(redp(aacc[r*4+0]), redp(aacc[r*4+1]),
                                   redp(aacc[r*4+2]), redp(aacc[r*4+3]));
            *(float4*)(a_sm + SWZ4(r0 + r, tx)) = v;
        }

        // ---- GRU: 6 table-driven passes ----
        {
            const float* srcs[6] = { a_sm, h_sm, h_sm, a_sm, a_sm, h_sm };
            float* t1 = s_sm;
            for (int p = 0; p < 6; p++) {
                const float4* wt4 = (const float4*)g_wt + (6 + p) * 1024;
                float4 wa = wt4[tid];
                float4 wb;
                if (has2) wb = wt4[640 + tid];
                __syncthreads();   // prev mm done; also orders a_sm stores (p==0)
                ((float4*)w_sm)[tid] = wa;
                if (has2) ((float4*)w_sm)[640 + tid] = wb;
                __syncthreads();
                unsigned long long acc2[20];
#pragma unroll
                for (int i = 0; i < 20; i++) acc2[i] = 0ull;
                mm5p(srcs[p], w_sm, r0, tx, acc2);
                float acc[20];
#pragma unroll
                for (int i = 0; i < 20; i++) acc[i] = redp(acc2[i]);

                if (p == 0 || p == 4) {            // raw -> t1
#pragma unroll
                    for (int r = 0; r < 5; r++)
                        *(float4*)(t1 + SWZ4(r0 + r, tx)) =
                            make_float4(acc[r*4+0], acc[r*4+1], acc[r*4+2], acc[r*4+3]);
                } else if (p == 2) {               // raw -> t2
#pragma unroll
                    for (int r = 0; r < 5; r++)
                        *(float4*)(t2_sm + SWZ4(r0 + r, tx)) =
                            make_float4(acc[r*4+0], acc[r*4+1], acc[r*4+2], acc[r*4+3]);
                } else if (p == 1 || p == 5) {     // gate = sigmoid(t1 + acc + b)
                    int b0 = (p == 1) ? 0 : 64;
                    float4 b1 = *(const float4*)(gbih + b0 + tx * 4);
                    float4 b2 = *(const float4*)(gbhh + b0 + tx * 4);
#pragma unroll
                    for (int r = 0; r < 5; r++) {
                        float4* tp = (float4*)(t1 + SWZ4(r0 + r, tx));
                        float4 o = *tp;
                        o.x = sigf(o.x + acc[r*4+0] + b1.x + b2.x);
                        o.y = sigf(o.y + acc[r*4+1] + b1.y + b2.y);
                        o.z = sigf(o.z + acc[r*4+2] + b1.z + b2.z);
                        o.w = sigf(o.w + acc[r*4+3] + b1.w + b2.w);
                        *tp = o;
                    }
                } else {                           // p==3: n = tanh(acc + bih + r*(t2 + bhh))
                    float4 b1 = *(const float4*)(gbih + 128 + tx * 4);
                    float4 b2 = *(const float4*)(gbhh + 128 + tx * 4);
#pragma unroll
                    for (int r = 0; r < 5; r++) {
                        float4* tp = (float4*)(t2_sm + SWZ4(r0 + r, tx));
                        float4 rg = *(const float4*)(t1 + SWZ4(r0 + r, tx));
                        float4 o = *tp;
                        o.x = tanhfast(acc[r*4+0] + b1.x + rg.x * (o.x + b2.x));
                        o.y = tanhfast(acc[r*4+1] + b1.y + rg.y * (o.y + b2.y));
                        o.z = tanhfast(acc[r*4+2] + b1.z + rg.z * (o.z + b2.z));
                        o.w = tanhfast(acc[r*4+3] + b1.w + rg.w * (o.w + b2.w));
                        *tp = o;
                    }
                }
            }
        }
        __syncthreads();
        // h = n + z*(h - n)    (t1 = z, t2 = n; identical linear layout)
        for (int i = tid; i < NPG * 16; i += NTH) {
            float4 z4 = ((const float4*)s_sm)[i];
            float4 n4 = ((const float4*)t2_sm)[i];
            float4 h4 = ((float4*)h_sm)[i];
            h4.x = fmaf(z4.x, h4.x - n4.x, n4.x);
            h4.y = fmaf(z4.y, h4.y - n4.y, n4.y);
            h4.z = fmaf(z4.z, h4.z - n4.z, n4.z);
            h4.w = fmaf(z4.w, h4.w - n4.w, n4.w);
            ((float4*)h_sm)[i] = h4;
        }
    }
    __syncthreads();

    // ---------- Set2Set readout ----------
    float* qstar = a_sm;
    float* hL    = a_sm + 128;
    float* cL    = a_sm + 320;
    float* gates = a_sm + 512;
    float* red   = a_sm + 768;
    float* part  = a_sm + 800;
    float* evals = s_sm;

    for (int i = tid; i < 512; i += NTH) a_sm[i] = 0.0f;
    __syncthreads();

    const float* WiA[3] = { wih0, wih1, wih2 };
    const float* WhA[3] = { whh0, whh1, whh2 };
    const float* biA[3] = { bih0, bih1, bih2 };
    const float* bhA[3] = { bhh0, bhh1, bhh2 };

    const int lane = tid & 31;
    const int wid = tid >> 5;

    for (int it = 0; it < 6; it++) {
        for (int l = 0; l < 3; l++) {
            const float* xin = (l == 0) ? qstar : (hL + (l - 1) * 64);
            int indim = (l == 0) ? 128 : 64;
            if (tid < 256) {
                float acc = biA[l][tid] + bhA[l][tid];
                const float* wr = WiA[l] + tid * indim;
                for (int j = 0; j < indim; j += 4) {
                    float4 wv = *(const float4*)(wr + j);
                    acc += xin[j] * wv.x + xin[j+1] * wv.y + xin[j+2] * wv.z + xin[j+3] * wv.w;
                }
                const float* wr2 = WhA[l] + tid * 64;
                const float* hin = hL + l * 64;
                for (int j = 0; j < 64; j += 4) {
                    float4 wv = *(const float4*)(wr2 + j);
                    acc += hin[j] * wv.x + hin[j+1] * wv.y + hin[j+2] * wv.z + hin[j+3] * wv.w;
                }
                gates[tid] = acc;
            }
            __syncthreads();
            if (tid < 64) {
                float gi = gates[tid], gf = gates[64 + tid], gg = gates[128 + tid], go = gates[192 + tid];
                float c = sigf(gf) * cL[l * 64 + tid] + sigf(gi) * tanhfast(gg);
                cL[l * 64 + tid] = c;
                hL[l * 64 + tid] = sigf(go) * tanhfast(c);
            }
            __syncthreads();
        }
        const float* q = hL + 128;
        float e = -3.4e38f;
        if (tid < NPG) {
            float acc = 0.0f;
#pragma unroll 4
            for (int c4 = 0; c4 < 16; c4++) {
                float4 hv = *(const float4*)(h_sm + SWZ4(tid, c4));
                float4 qv = *(const float4*)(q + c4 * 4);
                acc = fmaf(hv.x, qv.x, fmaf(hv.y, qv.y, fmaf(hv.z, qv.z, fmaf(hv.w, qv.w, acc))));
            }
            e = acc;
        }
        float m = e;
#pragma unroll
        for (int o = 16; o >= 1; o >>= 1) m = fmaxf(m, __shfl_xor_sync(0xffffffffu, m, o));
        if (lane == 0) red[wid] = m;
        __syncthreads();
        if (tid == 0) {
            float mm = red[0];
            for (int w = 1; w < 20; w++) mm = fmaxf(mm, red[w]);
            red[24] = mm;
        }
        __syncthreads();
        float bmax = red[24];
        float ex = (tid < NPG) ? __expf(e - bmax) : 0.0f;
        float ssum = ex;
#pragma unroll
        for (int o = 16; o >= 1; o >>= 1) ssum += __shfl_xor_sync(0xffffffffu, ssum, o);
        if (lane == 0) red[wid] = ssum;
        __syncthreads();
        if (tid == 0) {
            float sm = 0.0f;
            for (int w = 0; w < 20; w++) sm += red[w];
            red[25] = sm;
        }
        __syncthreads();
        float denom = red[25];
        if (tid < NPG) evals[tid] = ex / denom;
        __syncthreads();
        {
            int d = tid & 63, grp = tid >> 6;
            float acc = 0.0f;
            int nlo = grp * 20;
            for (int n = nlo; n < nlo + 20; n++)
                acc = fmaf(h_sm[SWZ4(n, d >> 2) + (d & 3)], evals[n], acc);
            part[grp * 64 + d] = acc;
        }
        __syncthreads();
        if (tid < 64) {
            float acc = 0.0f;
#pragma unroll
            for (int gg = 0; gg < 10; gg++) acc += part[gg * 64 + tid];
            qstar[64 + tid] = acc;
            qstar[tid] = q[tid];
        }
        __syncthreads();
    }

    if (tid < 3) {
        float acc = bp[tid];
        for (int j = 0; j < 128; j++) acc = fmaf(qstar[j], Wp[tid * 128 + j], acc);
        out[g * 3 + tid] = acc;
    }
}

extern "C" void kernel_launch(void* const* d_in, const int* in_sizes, int n_in,
                              void* d_out, int out_size) {
    const float* feats  = (const float*)d_in[0];
    const float* W_edge = (const float*)d_in[1];
    const float* b_edge = (const float*)d_in[2];
    const float* gWih   = (const float*)d_in[3];
    const float* gWhh   = (const float*)d_in[4];
    const float* gbih   = (const float*)d_in[5];
    const float* gbhh   = (const float*)d_in[6];
    const float* wih0 = (const float*)d_in[7];
    const float* whh0 = (const float*)d_in[8];
    const float* bih0 = (const float*)d_in[9];
    const float* bhh0 = (const float*)d_in[10];
    const float* wih1 = (const float*)d_in[11];
    const float* whh1 = (const float*)d_in[12];
    const float* bih1 = (const float*)d_in[13];
    const float* bhh1 = (const float*)d_in[14];
    const float* wih2 = (const float*)d_in[15];
    const float* whh2 = (const float*)d_in[16];
    const float* bih2 = (const float*)d_in[17];
    const float* bhh2 = (const float*)d_in[18];
    const float* Wp   = (const float*)d_in[19];
    const float* bp   = (const float*)d_in[20];
    const int* src    = (const int*)d_in[21];
    const int* dst    = (const int*)d_in[22];
    const int* ety    = (const int*)d_in[23];
    float* out = (float*)d_out;

    prep_kernel<<<192, 256>>>(W_edge, gWih, gWhh);

    cudaFuncSetAttribute(ggnn_fused_kernel,
                         cudaFuncAttributeMaxDynamicSharedMemorySize, SMEM_BYTES);

    ggnn_fused_kernel<<<320, NTH, SMEM_BYTES>>>(
        feats, b_edge, gbih, gbhh,
        wih0, whh0, bih0, bhh0,
        wih1, whh1, bih1, bhh1,
        wih2, whh2, bih2, bhh2,
        Wp, bp, src, dst, ety, out);
}

// round 5
// speedup vs baseline: 1.8778x; 1.8778x over previous
#include <cuda_runtime.h>
#include <math.h>

// GGNN + Set2Set. R5: per-step kernels, 2 half-graph CTAs per graph (occ 2),
// register-resident GRU gates, h ping-pong via global double buffer,
// edges counting-sorted once, weights pre-baked swizzled.

#define NPG   200
#define EPG   3200
#define NET   6
#define NGR   320          // graphs

// rotation swizzle: logical float4-col c4 of row at slot ((c4+row)&15)
#define SWZ4(row, c4) (((row)<<6) + ((((c4)+(row))&15)<<2))

// ---------------- global scratch (static: allowed) ----------------
__device__ float g_wt[12 * 4096];              // 12 swizzled 64x64 weight tiles
__device__ float g_hA[64000 * 64];             // h ping
__device__ float g_hB[64000 * 64];             // h pong
__device__ unsigned char  g_esrc[NGR * EPG];   // sorted src (local id)
__device__ unsigned short g_off[NGR * 1216];   // bucket offsets per graph

__device__ __forceinline__ float sigf(float x) { return 1.0f / (1.0f + __expf(-x)); }
__device__ __forceinline__ float tanhfast(float x) {
    x = fminf(fmaxf(x, -15.0f), 15.0f);
    float e = __expf(2.0f * x);
    return (e - 1.0f) / (e + 1.0f);
}

// 5x4 tile of (src[.x64] @ w[64x64]) added into acc (caller zeroes).
__device__ __forceinline__ void mm5(const float* __restrict__ src,
                                    const float* __restrict__ w,
                                    int r0, int tx, float* acc) {
#pragma unroll 4
    for (int db = 0; db < 16; db++) {
        int d0 = db * 4;
        float4 w0 = *(const float4*)(w + SWZ4(d0 + 0, tx));
        float4 w1 = *(const float4*)(w + SWZ4(d0 + 1, tx));
        float4 w2 = *(const float4*)(w + SWZ4(d0 + 2, tx));
        float4 w3 = *(const float4*)(w + SWZ4(d0 + 3, tx));
#pragma unroll
        for (int r = 0; r < 5; r++) {
            float4 xv = *(const float4*)(src + SWZ4(r0 + r, db));
            acc[r*4+0] = fmaf(xv.x, w0.x, fmaf(xv.y, w1.x, fmaf(xv.z, w2.x, fmaf(xv.w, w3.x, acc[r*4+0]))));
            acc[r*4+1] = fmaf(xv.x, w0.y, fmaf(xv.y, w1.y, fmaf(xv.z, w2.y, fmaf(xv.w, w3.y, acc[r*4+1]))));
            acc[r*4+2] = fmaf(xv.x, w0.z, fmaf(xv.y, w1.z, fmaf(xv.z, w2.z, fmaf(xv.w, w3.z, acc[r*4+2]))));
            acc[r*4+3] = fmaf(xv.x, w0.w, fmaf(xv.y, w1.w, fmaf(xv.z, w2.w, fmaf(xv.w, w3.w, acc[r*4+3]))));
        }
    }
}

// ---------------- prep: bake 12 swizzled weight tiles ----------------
// tiles 0..5 : W_edge[t], value(row=d, col=o) = W_edge[t][d][o]
// tiles 6..11: GRU slices, value(row=d, col=k) = M[g0+k][d]
//   order: 6=Wih_r 7=Whh_r 8=Whh_n 9=Wih_n 10=Wih_z 11=Whh_z
__global__ void prep_kernel(const float* __restrict__ W_edge,
                            const float* __restrict__ gWih,
                            const float* __restrict__ gWhh) {
    int i = blockIdx.x * blockDim.x + threadIdx.x;
    if (i >= 12 * 4096) return;
    int tile = i >> 12, r = i & 4095;
    int row = r >> 6, col = r & 63;    // row = d
    float v;
    if (tile < 6) {
        v = W_edge[(tile * 64 + row) * 64 + col];
    } else {
        int p = tile - 6;
        const int g0s[6] = { 0, 0, 128, 128, 64, 64 };
        const float* M = (p == 0 || p == 3 || p == 4) ? gWih : gWhh;
        v = M[(g0s[p] + col) * 64 + row];
    }
    g_wt[tile * 4096 + (row << 6) + ((((col >> 2) + row) & 15) << 2) + (col & 3)] = v;
}

// ---------------- sort: counting sort by (etype, dst) per graph ----------------
__global__ __launch_bounds__(640) void sort_kernel(
    const int* __restrict__ g_src, const int* __restrict__ g_dst,
    const int* __restrict__ g_ety) {
    __shared__ int cnt[1280];
    __shared__ int csum[256];
    const int tid = threadIdx.x;
    const int g = blockIdx.x;
    const int nbase = g * NPG, ebase = g * EPG;
    for (int i = tid; i < 1280; i += 640) cnt[i] = 0;
    __syncthreads();
    for (int e = tid; e < EPG; e += 640) {
        int key = g_ety[ebase + e] * NPG + (g_dst[ebase + e] - nbase);
        atomicAdd(&cnt[key], 1);
    }
    __syncthreads();
    if (tid < 256) {
        int s = 0;
#pragma unroll
        for (int j = 0; j < 5; j++) s += cnt[tid * 5 + j];
        csum[tid] = s;
    }
    __syncthreads();
    if (tid < 32) {
        int s = 0;
#pragma unroll
        for (int j = 0; j < 8; j++) s += csum[tid * 8 + j];
        int v = s;
        for (int o = 1; o < 32; o <<= 1) {
            int u = __shfl_up_sync(0xffffffffu, v, o);
            if (tid >= o) v += u;
        }
        int run = v - s;
#pragma unroll
        for (int j = 0; j < 8; j++) {
            int c = csum[tid * 8 + j];
            csum[tid * 8 + j] = run;
            run += c;
        }
    }
    __syncthreads();
    if (tid < 256) {
        int run = csum[tid];
#pragma unroll
        for (int j = 0; j < 5; j++) {
            int idx = tid * 5 + j;
            int c = cnt[idx];
            if (idx < 1216) g_off[g * 1216 + idx] = (unsigned short)run;
            run += c;
        }
    }
    __syncthreads();
    // rebuild cursors then scatter
    if (tid < 256) {
        int run = csum[tid];
#pragma unroll
        for (int j = 0; j < 5; j++) {
            int idx = tid * 5 + j;
            int c = cnt[idx];
            cnt[idx] = run;
            run += c;
        }
    }
    __syncthreads();
    for (int e = tid; e < EPG; e += 640) {
        int key = g_ety[ebase + e] * NPG + (g_dst[ebase + e] - nbase);
        int pos = atomicAdd(&cnt[key], 1);
        g_esrc[g * EPG + pos] = (unsigned char)(g_src[ebase + e] - nbase);
    }
}

// ---------------- one GGNN step: 640 CTAs (2 per graph), 320 threads ----------------
// SMEM floats: h_full 12800 | s 6400 | w 4096  then esrc 3200B, off 1216 u16
#define ST_H 0
#define ST_S 12800
#define ST_W 19200
#define ST_ESRC_BYTE (23296*4)
#define ST_OFF_BYTE  (ST_ESRC_BYTE + 3200)
#define ST_SMEM (ST_OFF_BYTE + 1216*2)    // 98816 bytes

__global__ __launch_bounds__(320, 2) void step_kernel(
    const float* __restrict__ feats,
    const float* __restrict__ b_edge,
    const float* __restrict__ gbih,
    const float* __restrict__ gbhh,
    int step) {
    extern __shared__ float smem[];
    float* h_sm = smem + ST_H;
    float* s_sm = smem + ST_S;
    float* w_sm = smem + ST_W;
    unsigned char*  esrc = (unsigned char*)smem + ST_ESRC_BYTE;
    unsigned short* off  = (unsigned short*)((char*)smem + ST_OFF_BYTE);

    const int tid = threadIdx.x;
    const int g = blockIdx.x >> 1;
    const int half = blockIdx.x & 1;
    const int nbase = g * NPG;
    const int tx = tid & 15;
    const int rt = tid >> 4;           // 0..19
    const int lr0 = rt * 5;            // local rows (0..99)
    const int gr0 = half * 100 + lr0;  // global rows in graph

    const float* hsrc = (step == 0) ? feats : ((step & 1) ? g_hA : g_hB);
    float* hdst = (step & 1) ? g_hB : g_hA;

    // load full h (swizzled), sorted edges, offsets
    for (int i = tid; i < 3200; i += 320) {
        int n = i >> 4, c4 = i & 15;
        *(float4*)(h_sm + SWZ4(n, c4)) =
            *(const float4*)(hsrc + (nbase + n) * 64 + c4 * 4);
    }
    {
        const unsigned int* es = (const unsigned int*)(g_esrc + g * EPG);
        unsigned int* ed = (unsigned int*)esrc;
        for (int i = tid; i < 800; i += 320) ed[i] = es[i];
        const unsigned int* os = (const unsigned int*)(g_off + g * 1216);
        unsigned int* od = (unsigned int*)off;
        for (int i = tid; i < 608; i += 320) od[i] = os[i];
    }

    // ---- a = sum_t (S_t @ W_t + cnt_t * b_t), acc in regs ----
    float aacc[20];
#pragma unroll
    for (int i = 0; i < 20; i++) aacc[i] = 0.0f;

    for (int t = 0; t < NET; t++) {
        __syncthreads();   // prior pass done with w_sm / s_sm (or initial loads done)
        {
            const float4* wsrc = (const float4*)g_wt + t * 1024;
            for (int i = tid; i < 1024; i += 320) ((float4*)w_sm)[i] = wsrc[i];
        }
        // aggregate s[n][:] for this half's dst rows
        {
            int dg = tid & 15, n = tid >> 4;   // n local 0..19, stride 20
            for (; n < 100; n += 20) {
                int b = t * NPG + half * 100 + n;
                int j0 = off[b], j1 = off[b + 1];
                float4 acc4 = make_float4(0.f, 0.f, 0.f, 0.f);
                for (int j = j0; j < j1; j++) {
                    float4 v = *(const float4*)(h_sm + SWZ4((int)esrc[j], dg));
                    acc4.x += v.x; acc4.y += v.y; acc4.z += v.z; acc4.w += v.w;
                }
                *(float4*)(s_sm + SWZ4(n, dg)) = acc4;
            }
        }
        __syncthreads();
        mm5(s_sm, w_sm, lr0, tx, aacc);
        float4 be = *(const float4*)(b_edge + t * 64 + tx * 4);
#pragma unroll
        for (int r = 0; r < 5; r++) {
            int b = t * NPG + half * 100 + lr0 + r;
            float cf = (float)(off[b + 1] - off[b]);
            aacc[r*4+0] = fmaf(cf, be.x, aacc[r*4+0]);
            aacc[r*4+1] = fmaf(cf, be.y, aacc[r*4+1]);
            aacc[r*4+2] = fmaf(cf, be.z, aacc[r*4+2]);
            aacc[r*4+3] = fmaf(cf, be.w, aacc[r*4+3]);
        }
    }
    __syncthreads();   // all mm reads of s done
    // materialize a into s_sm (local rows)
#pragma unroll
    for (int r = 0; r < 5; r++)
        *(float4*)(s_sm + SWZ4(lr0 + r, tx)) =
            make_float4(aacc[r*4+0], aacc[r*4+1], aacc[r*4+2], aacc[r*4+3]);

    // ---- GRU, gates in registers ----
#define STAGE(TILE) do { \
        __syncthreads(); \
        const float4* wsrc = (const float4*)g_wt + (TILE) * 1024; \
        for (int i = tid; i < 1024; i += 320) ((float4*)w_sm)[i] = wsrc[i]; \
        __syncthreads(); \
    } while (0)

    float accA[20], accB[20];

    // r = sigmoid(a@Wih_r + h@Whh_r + biases)
#pragma unroll
    for (int i = 0; i < 20; i++) accA[i] = 0.0f;
    STAGE(6);  mm5(s_sm, w_sm, lr0, tx, accA);
    STAGE(7);  mm5(h_sm, w_sm, gr0, tx, accA);
    float rg[20];
    {
        float4 b1 = *(const float4*)(gbih + tx * 4);
        float4 b2 = *(const float4*)(gbhh + tx * 4);
#pragma unroll
        for (int r = 0; r < 5; r++) {
            rg[r*4+0] = sigf(accA[r*4+0] + b1.x + b2.x);
            rg[r*4+1] = sigf(accA[r*4+1] + b1.y + b2.y);
            rg[r*4+2] = sigf(accA[r*4+2] + b1.z + b2.z);
            rg[r*4+3] = sigf(accA[r*4+3] + b1.w + b2.w);
        }
    }
    // n = tanh(a@Wih_n + bih_n + r * (h@Whh_n + bhh_n))
#pragma unroll
    for (int i = 0; i < 20; i++) accA[i] = 0.0f;
    STAGE(8);  mm5(h_sm, w_sm, gr0, tx, accA);      // hh_n
#pragma unroll
    for (int i = 0; i < 20; i++) accB[i] = 0.0f;
    STAGE(9);  mm5(s_sm, w_sm, lr0, tx, accB);      // ih_n
    {
        float4 b1 = *(const float4*)(gbih + 128 + tx * 4);
        float4 b2 = *(const float4*)(gbhh + 128 + tx * 4);
#pragma unroll
        for (int r = 0; r < 5; r++) {
            rg[r*4+0] = tanhfast(accB[r*4+0] + b1.x + rg[r*4+0] * (accA[r*4+0] + b2.x));
            rg[r*4+1] = tanhfast(accB[r*4+1] + b1.y + rg[r*4+1] * (accA[r*4+1] + b2.y));
            rg[r*4+2] = tanhfast(accB[r*4+2] + b1.z + rg[r*4+2] * (accA[r*4+2] + b2.z));
            rg[r*4+3] = tanhfast(accB[r*4+3] + b1.w + rg[r*4+3] * (accA[r*4+3] + b2.w));
        }
    }
    // z = sigmoid(a@Wih_z + h@Whh_z + biases)
#pragma unroll
    for (int i = 0; i < 20; i++) accA[i] = 0.0f;
    STAGE(10); mm5(s_sm, w_sm, lr0, tx, accA);
    STAGE(11); mm5(h_sm, w_sm, gr0, tx, accA);
    // h' = n + z*(h - n); write to global hdst (no smem hazard)
    {
        float4 b1 = *(const float4*)(gbih + 64 + tx * 4);
        float4 b2 = *(const float4*)(gbhh + 64 + tx * 4);
#pragma unroll
        for (int r = 0; r < 5; r++) {
            int grow = gr0 + r;
            float4 h4 = *(const float4*)(h_sm + SWZ4(grow, tx));
            float zx = sigf(accA[r*4+0] + b1.x + b2.x);
            float zy = sigf(accA[r*4+1] + b1.y + b2.y);
            float zz = sigf(accA[r*4+2] + b1.z + b2.z);
            float zw = sigf(accA[r*4+3] + b1.w + b2.w);
            float4 o;
            o.x = fmaf(zx, h4.x - rg[r*4+0], rg[r*4+0]);
            o.y = fmaf(zy, h4.y - rg[r*4+1], rg[r*4+1]);
            o.z = fmaf(zz, h4.z - rg[r*4+2], rg[r*4+2]);
            o.w = fmaf(zw, h4.w - rg[r*4+3], rg[r*4+3]);
            *(float4*)(hdst + (nbase + grow) * 64 + tx * 4) = o;
        }
    }
#undef STAGE
}

// ---------------- Set2Set: one CTA per graph, 320 threads ----------------
#define S2_H 0
#define S2_SCR 12800          // scratch floats
#define S2_SMEM ((12800 + 1536) * 4)

__global__ __launch_bounds__(320, 2) void set2set_kernel(
    const float* __restrict__ wih0, const float* __restrict__ whh0,
    const float* __restrict__ bih0, const float* __restrict__ bhh0,
    const float* __restrict__ wih1, const float* __restrict__ whh1,
    const float* __restrict__ bih1, const float* __restrict__ bhh1,
    const float* __restrict__ wih2, const float* __restrict__ whh2,
    const float* __restrict__ bih2, const float* __restrict__ bhh2,
    const float* __restrict__ Wp, const float* __restrict__ bp,
    float* __restrict__ out) {
    extern __shared__ float smem[];
    float* h_sm  = smem + S2_H;
    float* scr   = smem + S2_SCR;
    float* qstar = scr;          // 128
    float* hL    = scr + 128;    // 192
    float* cL    = scr + 320;    // 192
    float* gates = scr + 512;    // 256
    float* red   = scr + 768;    // 32
    float* part  = scr + 800;    // 320
    float* alpha = scr + 1120;   // 200 (fits: 1120+200=1320 <= 1536)

    const int tid = threadIdx.x;
    const int g = blockIdx.x;
    const int nbase = g * NPG;
    const int lane = tid & 31;
    const int wid = tid >> 5;    // 0..9

    for (int i = tid; i < 3200; i += 320) {
        int n = i >> 4, c4 = i & 15;
        *(float4*)(h_sm + SWZ4(n, c4)) =
            *(const float4*)(g_hA + (nbase + n) * 64 + c4 * 4);
    }
    for (int i = tid; i < 512; i += 320) scr[i] = 0.0f;
    __syncthreads();

    const float* WiA[3] = { wih0, wih1, wih2 };
    const float* WhA[3] = { whh0, whh1, whh2 };
    const float* biA[3] = { bih0, bih1, bih2 };
    const float* bhA[3] = { bhh0, bhh1, bhh2 };

    for (int it = 0; it < 6; it++) {
        for (int l = 0; l < 3; l++) {
            const float* xin = (l == 0) ? qstar : (hL + (l - 1) * 64);
            int indim = (l == 0) ? 128 : 64;
            if (tid < 256) {
                float acc = biA[l][tid] + bhA[l][tid];
                const float* wr = WiA[l] + tid * indim;
                for (int j = 0; j < indim; j += 4) {
                    float4 wv = *(const float4*)(wr + j);
                    acc += xin[j] * wv.x + xin[j+1] * wv.y + xin[j+2] * wv.z + xin[j+3] * wv.w;
                }
                const float* wr2 = WhA[l] + tid * 64;
                const float* hin = hL + l * 64;
                for (int j = 0; j < 64; j += 4) {
                    float4 wv = *(const float4*)(wr2 + j);
                    acc += hin[j] * wv.x + hin[j+1] * wv.y + hin[j+2] * wv.z + hin[j+3] * wv.w;
                }
                gates[tid] = acc;
            }
            __syncthreads();
            if (tid < 64) {
                float gi = gates[tid], gf = gates[64 + tid], gg = gates[128 + tid], go = gates[192 + tid];
                float c = sigf(gf) * cL[l * 64 + tid] + sigf(gi) * tanhfast(gg);
                cL[l * 64 + tid] = c;
                hL[l * 64 + tid] = sigf(go) * tanhfast(c);
            }
            __syncthreads();
        }
        const float* q = hL + 128;
        float e = -3.4e38f;
        if (tid < NPG) {
            float acc = 0.0f;
#pragma unroll 4
            for (int c4 = 0; c4 < 16; c4++) {
                float4 hv = *(const float4*)(h_sm + SWZ4(tid, c4));
                float4 qv = *(const float4*)(q + c4 * 4);
                acc = fmaf(hv.x, qv.x, fmaf(hv.y, qv.y, fmaf(hv.z, qv.z, fmaf(hv.w, qv.w, acc))));
            }
            e = acc;
        }
        float m = e;
#pragma unroll
        for (int o = 16; o >= 1; o >>= 1) m = fmaxf(m, __shfl_xor_sync(0xffffffffu, m, o));
        if (lane == 0) red[wid] = m;
        __syncthreads();
        if (tid == 0) {
            float mm = red[0];
            for (int w = 1; w < 10; w++) mm = fmaxf(mm, red[w]);
            red[16] = mm;
        }
        __syncthreads();
        float bmax = red[16];
        float ex = (tid < NPG) ? __expf(e - bmax) : 0.0f;
        float ssum = ex;
#pragma unroll
        for (int o = 16; o >= 1; o >>= 1) ssum += __shfl_xor_sync(0xffffffffu, ssum, o);
        if (lane == 0) red[wid] = ssum;
        __syncthreads();
        if (tid == 0) {
            float sm = 0.0f;
            for (int w = 0; w < 10; w++) sm += red[w];
            red[17] = sm;
        }
        __syncthreads();
        float denom = red[17];
        if (tid < NPG) alpha[tid] = ex / denom;
        __syncthreads();
        {
            int d = tid & 63, grp = tid >> 6;   // grp 0..4, 40 nodes each
            float acc = 0.0f;
            int nlo = grp * 40;
            for (int n = nlo; n < nlo + 40; n++)
                acc = fmaf(h_sm[SWZ4(n, d >> 2) + (d & 3)], alpha[n], acc);
            part[grp * 64 + d] = acc;
        }
        __syncthreads();
        if (tid < 64) {
            float acc = 0.0f;
#pragma unroll
            for (int gg = 0; gg < 5; gg++) acc += part[gg * 64 + tid];
            qstar[64 + tid] = acc;
            qstar[tid] = q[tid];
        }
        __syncthreads();
    }

    if (tid < 3) {
        float acc = bp[tid];
        for (int j = 0; j < 128; j++) acc = fmaf(qstar[j], Wp[tid * 128 + j], acc);
        out[g * 3 + tid] = acc;
    }
}

extern "C" void kernel_launch(void* const* d_in, const int* in_sizes, int n_in,
                              void* d_out, int out_size) {
    const float* feats  = (const float*)d_in[0];
    const float* W_edge = (const float*)d_in[1];
    const float* b_edge = (const float*)d_in[2];
    const float* gWih   = (const float*)d_in[3];
    const float* gWhh   = (const float*)d_in[4];
    const float* gbih   = (const float*)d_in[5];
    const float* gbhh   = (const float*)d_in[6];
    const float* wih0 = (const float*)d_in[7];
    const float* whh0 = (const float*)d_in[8];
    const float* bih0 = (const float*)d_in[9];
    const float* bhh0 = (const float*)d_in[10];
    const float* wih1 = (const float*)d_in[11];
    const float* whh1 = (const float*)d_in[12];
    const float* bih1 = (const float*)d_in[13];
    const float* bhh1 = (const float*)d_in[14];
    const float* wih2 = (const float*)d_in[15];
    const float* whh2 = (const float*)d_in[16];
    const float* bih2 = (const float*)d_in[17];
    const float* bhh2 = (const float*)d_in[18];
    const float* Wp   = (const float*)d_in[19];
    const float* bp   = (const float*)d_in[20];
    const int* src    = (const int*)d_in[21];
    const int* dst    = (const int*)d_in[22];
    const int* ety    = (const int*)d_in[23];
    float* out = (float*)d_out;

    static int inited = 0;
    if (!inited) {
        cudaFuncSetAttribute(step_kernel,
                             cudaFuncAttributeMaxDynamicSharedMemorySize, ST_SMEM);
        cudaFuncSetAttribute(set2set_kernel,
                             cudaFuncAttributeMaxDynamicSharedMemorySize, S2_SMEM);
        inited = 1;
    }

    prep_kernel<<<192, 256>>>(W_edge, gWih, gWhh);
    sort_kernel<<<NGR, 640>>>(src, dst, ety);
    for (int s = 0; s < 5; s++)
        step_kernel<<<NGR * 2, 320, ST_SMEM>>>(feats, b_edge, gbih, gbhh, s);
    set2set_kernel<<<NGR, 320, S2_SMEM>>>(
        wih0, whh0, bih0, bhh0,
        wih1, whh1, bih1, bhh1,
        wih2, whh2, bih2, bhh2,
        Wp, bp, out);
}

// round 6
// speedup vs baseline: 3.0075x; 1.6016x over previous
#include <cuda_runtime.h>
#include <cuda_bf16.h>
#include <math.h>

// GGNN + Set2Set. R6: step matmuls on tensor cores (mma.sync m16n8k16 bf16,
// bf16x3 split, fp32 accum). Half-graph CTAs (640) x 448 threads, occ 2.
// Weights pre-baked in B-fragment order (hi/lo). h kept as bf16 hi/lo pair.

#define NPG 200
#define EPG 3200
#define NET 6
#define NGR 320
#define NTH 448

// ---- step kernel SMEM layout (bytes) ----
#define HP_HI 0                 // h hi: 216 rows x 128B
#define HP_LO 27648             // h lo
#define SP_HI 55296             // s/a hi: 112 rows x 128B
#define SP_LO 69632
#define WB    83968             // staged B fragments: 16384B
#define ESRCB 100352            // 3200B sorted src (u8)
#define OFFLB 103552            // 606 u16 own-half offsets (pad 1216B)
#define ST_SMEM 104768

// ---------------- global scratch ----------------
__device__ float g_hA[64000 * 64];
__device__ float g_hB[64000 * 64];
__device__ unsigned char  g_esrc[NGR * EPG];
__device__ unsigned short g_off[NGR * 1216];
// B fragments: [tile 0..11][split 0=hi,1=lo][ntg 0..7][ks 0..3][lane][reg] u32
__device__ unsigned int g_wfrag[12 * 4096];

__device__ __forceinline__ float sigf(float x) { return 1.0f / (1.0f + __expf(-x)); }
__device__ __forceinline__ float tanhfast(float x) {
    x = fminf(fmaxf(x, -15.0f), 15.0f);
    float e = __expf(2.0f * x);
    return (e - 1.0f) / (e + 1.0f);
}
__device__ __forceinline__ float blo(unsigned w) { return __uint_as_float(w << 16); }
__device__ __forceinline__ float bhi(unsigned w) { return __uint_as_float(w & 0xffff0000u); }
// pack (a -> low half, b -> high half) as bf16 hi word + bf16 residual lo word
__device__ __forceinline__ void cvtpair(float a, float b, unsigned& hi, unsigned& lo) {
    asm("cvt.rn.bf16x2.f32 %0, %1, %2;" : "=r"(hi) : "f"(b), "f"(a));
    float fa = blo(hi), fb = bhi(hi);
    asm("cvt.rn.bf16x2.f32 %0, %1, %2;" : "=r"(lo) : "f"(b - fb), "f"(a - fa));
}
__device__ __forceinline__ unsigned smem_u32(const void* p) {
    unsigned a;
    asm("{ .reg .u64 t; cvta.to.shared.u64 t, %1; cvt.u32.u64 %0, t; }" : "=r"(a) : "l"(p));
    return a;
}
__device__ __forceinline__ void ldmA(unsigned addr, unsigned r[4]) {
    asm volatile("ldmatrix.sync.aligned.m8n8.x4.shared.b16 {%0,%1,%2,%3}, [%4];"
                 : "=r"(r[0]), "=r"(r[1]), "=r"(r[2]), "=r"(r[3]) : "r"(addr));
}
__device__ __forceinline__ void mma16816(float* c, const unsigned a[4], unsigned b0, unsigned b1) {
    asm volatile("mma.sync.aligned.m16n8k16.row.col.f32.bf16.bf16.f32 "
                 "{%0,%1,%2,%3}, {%4,%5,%6,%7}, {%8,%9}, {%0,%1,%2,%3};"
                 : "+f"(c[0]), "+f"(c[1]), "+f"(c[2]), "+f"(c[3])
                 : "r"(a[0]), "r"(a[1]), "r"(a[2]), "r"(a[3]), "r"(b0), "r"(b1));
}

// ---------------- prep: bake B fragments (hi+lo) ----------------
// out[m,n] = sum_k A[m,k]*B[k][n].  etype t: B[k][n] = W_edge[t][k][n].
// GRU p: B[k][n] = M_p[g0_p + n][k].  tiles 6..11 = ihr,hhr,hhn,ihn,ihz,hhz.
__global__ void prep_kernel(const float* __restrict__ W_edge,
                            const float* __restrict__ gWih,
                            const float* __restrict__ gWhh) {
    int i = blockIdx.x * blockDim.x + threadIdx.x;   // 24576 items (both halves)
    if (i >= 24576) return;
    int reg = i & 1, lane = (i >> 1) & 31, ks = (i >> 6) & 3;
    int ntg = (i >> 8) & 7, tile = i >> 11;
    int n = ntg * 8 + (lane >> 2);
    int k = ks * 16 + (lane & 3) * 2 + reg * 8;      // word holds k, k+1
    float w0, w1;
    if (tile < 6) {
        w0 = W_edge[(tile * 64 + k) * 64 + n];
        w1 = W_edge[(tile * 64 + k + 1) * 64 + n];
    } else {
        int p = tile - 6;
        const int g0s[6] = { 0, 0, 128, 128, 64, 64 };
        const float* M = (p == 0 || p == 3 || p == 4) ? gWih : gWhh;
        w0 = M[(g0s[p] + n) * 64 + k];
        w1 = M[(g0s[p] + n) * 64 + k + 1];
    }
    unsigned hw, lw;
    cvtpair(w0, w1, hw, lw);
    int base = tile * 4096 + (ntg * 4 + ks) * 64 + lane * 2 + reg;
    g_wfrag[base] = hw;              // split 0
    g_wfrag[base + 2048] = lw;       // split 1 (8 ntg * 4 ks * 64 = 2048)
}

// ---------------- sort: counting sort by (etype, dst) per graph ----------------
__global__ __launch_bounds__(640) void sort_kernel(
    const int* __restrict__ g_src, const int* __restrict__ g_dst,
    const int* __restrict__ g_ety) {
    __shared__ int cnt[1280];
    __shared__ int csum[256];
    const int tid = threadIdx.x;
    const int g = blockIdx.x;
    const int nbase = g * NPG, ebase = g * EPG;
    for (int i = tid; i < 1280; i += 640) cnt[i] = 0;
    __syncthreads();
    for (int e = tid; e < EPG; e += 640) {
        int key = g_ety[ebase + e] * NPG + (g_dst[ebase + e] - nbase);
        atomicAdd(&cnt[key], 1);
    }
    __syncthreads();
    if (tid < 256) {
        int s = 0;
#pragma unroll
        for (int j = 0; j < 5; j++) s += cnt[tid * 5 + j];
        csum[tid] = s;
    }
    __syncthreads();
    if (tid < 32) {
        int s = 0;
#pragma unroll
        for (int j = 0; j < 8; j++) s += csum[tid * 8 + j];
        int v = s;
        for (int o = 1; o < 32; o <<= 1) {
            int u = __shfl_up_sync(0xffffffffu, v, o);
            if (tid >= o) v += u;
        }
        int run = v - s;
#pragma unroll
        for (int j = 0; j < 8; j++) {
            int c = csum[tid * 8 + j];
            csum[tid * 8 + j] = run;
            run += c;
        }
    }
    __syncthreads();
    if (tid < 256) {
        int run = csum[tid];
#pragma unroll
        for (int j = 0; j < 5; j++) {
            int idx = tid * 5 + j;
            int c = cnt[idx];
            if (idx < 1216) g_off[g * 1216 + idx] = (unsigned short)run;
            run += c;
        }
    }
    __syncthreads();
    if (tid < 256) {
        int run = csum[tid];
#pragma unroll
        for (int j = 0; j < 5; j++) {
            int idx = tid * 5 + j;
            int c = cnt[idx];
            cnt[idx] = run;
            run += c;
        }
    }
    __syncthreads();
    for (int e = tid; e < EPG; e += 640) {
        int key = g_ety[ebase + e] * NPG + (g_dst[ebase + e] - nbase);
        int pos = atomicAdd(&cnt[key], 1);
        g_esrc[g * EPG + pos] = (unsigned char)(g_src[ebase + e] - nbase);
    }
}

// ---------------- step kernel ----------------
__global__ __launch_bounds__(NTH, 2) void step_kernel(
    const float* __restrict__ feats,
    const float* __restrict__ b_edge,
    const float* __restrict__ gbih,
    const float* __restrict__ gbhh,
    int step) {
    extern __shared__ char sm[];
    unsigned smb = smem_u32(sm);
    unsigned char* esrc = (unsigned char*)(sm + ESRCB);
    unsigned short* offl = (unsigned short*)(sm + OFFLB);

    const int tid = threadIdx.x;
    const int g = blockIdx.x >> 1;
    const int half = blockIdx.x & 1;
    const int lane = tid & 31;
    const int wid = tid >> 5;          // 0..13
    const int mt = wid >> 1;           // 0..6
    const int nh = wid & 1;
    const int lrow = mt * 16 + (lane & 15);        // local row for ldmatrix (sp)
    const int hrow = half * 100 + lrow;            // graph row (hp)
    const int lmt = lane >> 4;                     // k-unit parity
    const int g8 = lane >> 2, q = lane & 3;
    const int r1l = mt * 16 + g8, r2l = r1l + 8;   // C-fragment local rows

    const float* hsrc = (step == 0) ? feats : ((step & 1) ? g_hA : g_hB);
    float* hdst = (step & 1) ? g_hB : g_hA;

    // ---- load: h -> bf16 pair (full graph), esrc, own-half offsets ----
    for (int i = tid; i < 1600; i += NTH) {
        int n = i >> 3, u = i & 7;
        const float4* src = (const float4*)(hsrc + (g * NPG + n) * 64 + u * 8);
        float4 v0 = src[0], v1 = src[1];
        unsigned hw0, lw0, hw1, lw1, hw2, lw2, hw3, lw3;
        cvtpair(v0.x, v0.y, hw0, lw0);
        cvtpair(v0.z, v0.w, hw1, lw1);
        cvtpair(v1.x, v1.y, hw2, lw2);
        cvtpair(v1.z, v1.w, hw3, lw3);
        int bo = n * 128 + (((u + n) & 7) << 4);
        *(uint4*)(sm + HP_HI + bo) = make_uint4(hw0, hw1, hw2, hw3);
        *(uint4*)(sm + HP_LO + bo) = make_uint4(lw0, lw1, lw2, lw3);
    }
    {
        const uint4* es = (const uint4*)(g_esrc + g * EPG);
        for (int i = tid; i < 200; i += NTH) ((uint4*)esrc)[i] = es[i];
        for (int j = tid; j < 606; j += NTH) {
            int t = j / 101, i2 = j % 101;
            offl[j] = g_off[g * 1216 + t * 200 + half * 100 + i2];
        }
    }

    // ---- etype passes: aC = sum_t (S_t @ W_t) in C fragments ----
    float aC[16];
#pragma unroll
    for (int i = 0; i < 16; i++) aC[i] = 0.0f;

    for (int t = 0; t < NET; t++) {
        // prefetch B fragments (16KB = 1024 uint4)
        const uint4* ws = (const uint4*)g_wfrag + t * 1024;
        uint4 w0 = ws[tid], w1 = ws[tid + 448], w2;
        if (tid < 128) w2 = ws[tid + 896];
        __syncthreads();
        ((uint4*)(sm + WB))[tid] = w0;
        ((uint4*)(sm + WB))[tid + 448] = w1;
        if (tid < 128) ((uint4*)(sm + WB))[tid + 896] = w2;
        // aggregate s (own half) from h bf16 pair; write bf16 pair
        for (int i = tid; i < 800; i += NTH) {
            int n = i >> 3, u = i & 7;
            int b = t * 101 + n;
            int j0 = offl[b], j1 = offl[b + 1];
            float a0 = 0, a1 = 0, a2 = 0, a3 = 0, a4 = 0, a5 = 0, a6 = 0, a7 = 0;
            for (int j = j0; j < j1; j++) {
                int er = esrc[j];
                int bo = er * 128 + (((u + er) & 7) << 4);
                uint4 H = *(const uint4*)(sm + HP_HI + bo);
                uint4 L = *(const uint4*)(sm + HP_LO + bo);
                a0 += blo(H.x) + blo(L.x);  a1 += bhi(H.x) + bhi(L.x);
                a2 += blo(H.y) + blo(L.y);  a3 += bhi(H.y) + bhi(L.y);
                a4 += blo(H.z) + blo(L.z);  a5 += bhi(H.z) + bhi(L.z);
                a6 += blo(H.w) + blo(L.w);  a7 += bhi(H.w) + bhi(L.w);
            }
            unsigned hw0, lw0, hw1, lw1, hw2, lw2, hw3, lw3;
            cvtpair(a0, a1, hw0, lw0);
            cvtpair(a2, a3, hw1, lw1);
            cvtpair(a4, a5, hw2, lw2);
            cvtpair(a6, a7, hw3, lw3);
            int bo = n * 128 + (((u + n) & 7) << 4);
            *(uint4*)(sm + SP_HI + bo) = make_uint4(hw0, hw1, hw2, hw3);
            *(uint4*)(sm + SP_LO + bo) = make_uint4(lw0, lw1, lw2, lw3);
        }
        __syncthreads();
        // mm: aC += s @ W_t  (bf16x3)
#pragma unroll
        for (int ks = 0; ks < 4; ks++) {
            int unit = 2 * ks + lmt;
            unsigned ah[4], al[4];
            ldmA(smb + SP_HI + lrow * 128 + (((unit + lrow) & 7) << 4), ah);
            ldmA(smb + SP_LO + lrow * 128 + (((unit + lrow) & 7) << 4), al);
#pragma unroll
            for (int nt = 0; nt < 4; nt++) {
                int ntg = nh * 4 + nt;
                uint2 bh = *(const uint2*)(sm + WB + (((ntg * 4 + ks) * 64) + lane * 2) * 4);
                uint2 bl = *(const uint2*)(sm + WB + ((2048 + (ntg * 4 + ks) * 64) + lane * 2) * 4);
                mma16816(aC + nt * 4, al, bh.x, bh.y);
                mma16816(aC + nt * 4, ah, bl.x, bl.y);
                mma16816(aC + nt * 4, ah, bh.x, bh.y);
            }
        }
    }
    // bias: aC += cnt_t(row) * b_edge[t][col]
#pragma unroll
    for (int t = 0; t < NET; t++) {
        float c1 = (r1l < 100) ? (float)(offl[t * 101 + r1l + 1] - offl[t * 101 + r1l]) : 0.0f;
        float c2 = (r2l < 100) ? (float)(offl[t * 101 + r2l + 1] - offl[t * 101 + r2l]) : 0.0f;
#pragma unroll
        for (int nt = 0; nt < 4; nt++) {
            int col = nh * 32 + nt * 8 + q * 2;
            float2 b = *(const float2*)(b_edge + t * 64 + col);
            aC[nt * 4 + 0] = fmaf(c1, b.x, aC[nt * 4 + 0]);
            aC[nt * 4 + 1] = fmaf(c1, b.y, aC[nt * 4 + 1]);
            aC[nt * 4 + 2] = fmaf(c2, b.x, aC[nt * 4 + 2]);
            aC[nt * 4 + 3] = fmaf(c2, b.y, aC[nt * 4 + 3]);
        }
    }
    __syncthreads();   // all warps done reading sp (last etype mm)
    // write a -> sp bf16 pair
#pragma unroll
    for (int nt = 0; nt < 4; nt++) {
        int col = nh * 32 + nt * 8 + q * 2;
        int u = col >> 3;
        unsigned hw, lw;
        cvtpair(aC[nt * 4 + 0], aC[nt * 4 + 1], hw, lw);
        int bo1 = r1l * 128 + (((u + r1l) & 7) << 4) + q * 4;
        *(unsigned*)(sm + SP_HI + bo1) = hw;
        *(unsigned*)(sm + SP_LO + bo1) = lw;
        cvtpair(aC[nt * 4 + 2], aC[nt * 4 + 3], hw, lw);
        int bo2 = r2l * 128 + (((u + r2l) & 7) << 4) + q * 4;
        *(unsigned*)(sm + SP_HI + bo2) = hw;
        *(unsigned*)(sm + SP_LO + bo2) = lw;
    }

    // ---- GRU ----
#define STAGEW(T) do { \
        const uint4* ws_ = (const uint4*)g_wfrag + (T) * 1024; \
        uint4 s0 = ws_[tid], s1 = ws_[tid + 448], s2; \
        if (tid < 128) s2 = ws_[tid + 896]; \
        __syncthreads(); \
        ((uint4*)(sm + WB))[tid] = s0; \
        ((uint4*)(sm + WB))[tid + 448] = s1; \
        if (tid < 128) ((uint4*)(sm + WB))[tid + 896] = s2; \
        __syncthreads(); \
    } while (0)

#define MMPASS(BASE_HI, BASE_LO, ROW, C) do { \
        _Pragma("unroll") \
        for (int ks = 0; ks < 4; ks++) { \
            int unit = 2 * ks + lmt; \
            unsigned ah[4], al[4]; \
            ldmA(smb + (BASE_HI) + (ROW) * 128 + (((unit + (ROW)) & 7) << 4), ah); \
            ldmA(smb + (BASE_LO) + (ROW) * 128 + (((unit + (ROW)) & 7) << 4), al); \
            _Pragma("unroll") \
            for (int nt = 0; nt < 4; nt++) { \
                int ntg = nh * 4 + nt; \
                uint2 bh = *(const uint2*)(sm + WB + (((ntg * 4 + ks) * 64) + lane * 2) * 4); \
                uint2 bl = *(const uint2*)(sm + WB + ((2048 + (ntg * 4 + ks) * 64) + lane * 2) * 4); \
                mma16816((C) + nt * 4, al, bh.x, bh.y); \
                mma16816((C) + nt * 4, ah, bl.x, bl.y); \
                mma16816((C) + nt * 4, ah, bh.x, bh.y); \
            } \
        } \
    } while (0)

    float C[16], rg[16];
    // r = sigmoid(a@Wih_r + h@Whh_r + b)
#pragma unroll
    for (int i = 0; i < 16; i++) C[i] = 0.0f;
    STAGEW(6);  MMPASS(SP_HI, SP_LO, lrow, C);
    STAGEW(7);  MMPASS(HP_HI, HP_LO, hrow, C);
#pragma unroll
    for (int nt = 0; nt < 4; nt++) {
        int col = nh * 32 + nt * 8 + q * 2;
        float2 bi = *(const float2*)(gbih + col);
        float2 bh = *(const float2*)(gbhh + col);
        rg[nt * 4 + 0] = sigf(C[nt * 4 + 0] + bi.x + bh.x);
        rg[nt * 4 + 1] = sigf(C[nt * 4 + 1] + bi.y + bh.y);
        rg[nt * 4 + 2] = sigf(C[nt * 4 + 2] + bi.x + bh.x);
        rg[nt * 4 + 3] = sigf(C[nt * 4 + 3] + bi.y + bh.y);
    }
    // t = r * (h@Whh_n + bhh_n)
#pragma unroll
    for (int i = 0; i < 16; i++) C[i] = 0.0f;
    STAGEW(8);  MMPASS(HP_HI, HP_LO, hrow, C);
#pragma unroll
    for (int nt = 0; nt < 4; nt++) {
        int col = nh * 32 + nt * 8 + q * 2;
        float2 bh = *(const float2*)(gbhh + 128 + col);
        rg[nt * 4 + 0] *= (C[nt * 4 + 0] + bh.x);
        rg[nt * 4 + 1] *= (C[nt * 4 + 1] + bh.y);
        rg[nt * 4 + 2] *= (C[nt * 4 + 2] + bh.x);
        rg[nt * 4 + 3] *= (C[nt * 4 + 3] + bh.y);
    }
    // n = tanh(a@Wih_n + bih_n + t)
#pragma unroll
    for (int i = 0; i < 16; i++) C[i] = 0.0f;
    STAGEW(9);  MMPASS(SP_HI, SP_LO, lrow, C);
#pragma unroll
    for (int nt = 0; nt < 4; nt++) {
        int col = nh * 32 + nt * 8 + q * 2;
        float2 bi = *(const float2*)(gbih + 128 + col);
        rg[nt * 4 + 0] = tanhfast(C[nt * 4 + 0] + bi.x + rg[nt * 4 + 0]);
        rg[nt * 4 + 1] = tanhfast(C[nt * 4 + 1] + bi.y + rg[nt * 4 + 1]);
        rg[nt * 4 + 2] = tanhfast(C[nt * 4 + 2] + bi.x + rg[nt * 4 + 2]);
        rg[nt * 4 + 3] = tanhfast(C[nt * 4 + 3] + bi.y + rg[nt * 4 + 3]);
    }
    // z = sigmoid(a@Wih_z + h@Whh_z + b); h' = n + z*(h - n)
#pragma unroll
    for (int i = 0; i < 16; i++) C[i] = 0.0f;
    STAGEW(10); MMPASS(SP_HI, SP_LO, lrow, C);
    STAGEW(11); MMPASS(HP_HI, HP_LO, hrow, C);
#pragma unroll
    for (int nt = 0; nt < 4; nt++) {
        int col = nh * 32 + nt * 8 + q * 2;
        int u = col >> 3;
        float2 bi = *(const float2*)(gbih + 64 + col);
        float2 bh2 = *(const float2*)(gbhh + 64 + col);
        if (r1l < 100) {
            int gr = half * 100 + r1l;
            int bo = gr * 128 + (((u + gr) & 7) << 4) + q * 4;
            unsigned hw = *(const unsigned*)(sm + HP_HI + bo);
            unsigned lw = *(const unsigned*)(sm + HP_LO + bo);
            float h0 = blo(hw) + blo(lw), h1 = bhi(hw) + bhi(lw);
            float z0 = sigf(C[nt * 4 + 0] + bi.x + bh2.x);
            float z1 = sigf(C[nt * 4 + 1] + bi.y + bh2.y);
            float n0 = rg[nt * 4 + 0], n1 = rg[nt * 4 + 1];
            float2 o;
            o.x = fmaf(z0, h0 - n0, n0);
            o.y = fmaf(z1, h1 - n1, n1);
            *(float2*)(hdst + (g * NPG + gr) * 64 + col) = o;
        }
        if (r2l < 100) {
            int gr = half * 100 + r2l;
            int bo = gr * 128 + (((u + gr) & 7) << 4) + q * 4;
            unsigned hw = *(const unsigned*)(sm + HP_HI + bo);
            unsigned lw = *(const unsigned*)(sm + HP_LO + bo);
            float h0 = blo(hw) + blo(lw), h1 = bhi(hw) + bhi(lw);
            float z0 = sigf(C[nt * 4 + 2] + bi.x + bh2.x);
            float z1 = sigf(C[nt * 4 + 3] + bi.y + bh2.y);
            float n0 = rg[nt * 4 + 2], n1 = rg[nt * 4 + 3];
            float2 o;
            o.x = fmaf(z0, h0 - n0, n0);
            o.y = fmaf(z1, h1 - n1, n1);
            *(float2*)(hdst + (g * NPG + gr) * 64 + col) = o;
        }
    }
#undef STAGEW
#undef MMPASS
}

// ---------------- Set2Set: one CTA per graph, 320 threads (from R5) ----------------
#define SWZ4(row, c4) (((row)<<6) + ((((c4)+(row))&15)<<2))
#define S2_H 0
#define S2_SCR 12800
#define S2_SMEM ((12800 + 1536) * 4)

__global__ __launch_bounds__(320, 2) void set2set_kernel(
    const float* __restrict__ wih0, const float* __restrict__ whh0,
    const float* __restrict__ bih0, const float* __restrict__ bhh0,
    const float* __restrict__ wih1, const float* __restrict__ whh1,
    const float* __restrict__ bih1, const float* __restrict__ bhh1,
    const float* __restrict__ wih2, const float* __restrict__ whh2,
    const float* __restrict__ bih2, const float* __restrict__ bhh2,
    const float* __restrict__ Wp, const float* __restrict__ bp,
    float* __restrict__ out) {
    extern __shared__ float smem[];
    float* h_sm  = smem + S2_H;
    float* scr   = smem + S2_SCR;
    float* qstar = scr;
    float* hL    = scr + 128;
    float* cL    = scr + 320;
    float* gates = scr + 512;
    float* red   = scr + 768;
    float* part  = scr + 800;
    float* alpha = scr + 1120;

    const int tid = threadIdx.x;
    const int g = blockIdx.x;
    const int nbase = g * NPG;
    const int lane = tid & 31;
    const int wid = tid >> 5;

    for (int i = tid; i < 3200; i += 320) {
        int n = i >> 4, c4 = i & 15;
        *(float4*)(h_sm + SWZ4(n, c4)) =
            *(const float4*)(g_hA + (nbase + n) * 64 + c4 * 4);
    }
    for (int i = tid; i < 512; i += 320) scr[i] = 0.0f;
    __syncthreads();

    const float* WiA[3] = { wih0, wih1, wih2 };
    const float* WhA[3] = { whh0, whh1, whh2 };
    const float* biA[3] = { bih0, bih1, bih2 };
    const float* bhA[3] = { bhh0, bhh1, bhh2 };

    for (int it = 0; it < 6; it++) {
        for (int l = 0; l < 3; l++) {
            const float* xin = (l == 0) ? qstar : (hL + (l - 1) * 64);
            int indim = (l == 0) ? 128 : 64;
            if (tid < 256) {
                float acc = biA[l][tid] + bhA[l][tid];
                const float* wr = WiA[l] + tid * indim;
                for (int j = 0; j < indim; j += 4) {
                    float4 wv = *(const float4*)(wr + j);
                    acc += xin[j] * wv.x + xin[j+1] * wv.y + xin[j+2] * wv.z + xin[j+3] * wv.w;
                }
                const float* wr2 = WhA[l] + tid * 64;
                const float* hin = hL + l * 64;
                for (int j = 0; j < 64; j += 4) {
                    float4 wv = *(const float4*)(wr2 + j);
                    acc += hin[j] * wv.x + hin[j+1] * wv.y + hin[j+2] * wv.z + hin[j+3] * wv.w;
                }
                gates[tid] = acc;
            }
            __syncthreads();
            if (tid < 64) {
                float gi = gates[tid], gf = gates[64 + tid], gg = gates[128 + tid], go = gates[192 + tid];
                float c = sigf(gf) * cL[l * 64 + tid] + sigf(gi) * tanhfast(gg);
                cL[l * 64 + tid] = c;
                hL[l * 64 + tid] = sigf(go) * tanhfast(c);
            }
            __syncthreads();
        }
        const float* q = hL + 128;
        float e = -3.4e38f;
        if (tid < NPG) {
            float acc = 0.0f;
#pragma unroll 4
            for (int c4 = 0; c4 < 16; c4++) {
                float4 hv = *(const float4*)(h_sm + SWZ4(tid, c4));
                float4 qv = *(const float4*)(q + c4 * 4);
                acc = fmaf(hv.x, qv.x, fmaf(hv.y, qv.y, fmaf(hv.z, qv.z, fmaf(hv.w, qv.w, acc))));
            }
            e = acc;
        }
        float m = e;
#pragma unroll
        for (int o = 16; o >= 1; o >>= 1) m = fmaxf(m, __shfl_xor_sync(0xffffffffu, m, o));
        if (lane == 0) red[wid] = m;
        __syncthreads();
        if (tid == 0) {
            float mm = red[0];
            for (int w = 1; w < 10; w++) mm = fmaxf(mm, red[w]);
            red[16] = mm;
        }
        __syncthreads();
        float bmax = red[16];
        float ex = (tid < NPG) ? __expf(e - bmax) : 0.0f;
        float ssum = ex;
#pragma unroll
        for (int o = 16; o >= 1; o >>= 1) ssum += __shfl_xor_sync(0xffffffffu, ssum, o);
        if (lane == 0) red[wid] = ssum;
        __syncthreads();
        if (tid == 0) {
            float sm2 = 0.0f;
            for (int w = 0; w < 10; w++) sm2 += red[w];
            red[17] = sm2;
        }
        __syncthreads();
        float denom = red[17];
        if (tid < NPG) alpha[tid] = ex / denom;
        __syncthreads();
        {
            int d = tid & 63, grp = tid >> 6;
            float acc = 0.0f;
            int nlo = grp * 40;
            for (int n = nlo; n < nlo + 40; n++)
                acc = fmaf(h_sm[SWZ4(n, d >> 2) + (d & 3)], alpha[n], acc);
            part[grp * 64 + d] = acc;
        }
        __syncthreads();
        if (tid < 64) {
            float acc = 0.0f;
#pragma unroll
            for (int gg = 0; gg < 5; gg++) acc += part[gg * 64 + tid];
            qstar[64 + tid] = acc;
            qstar[tid] = q[tid];
        }
        __syncthreads();
    }

    if (tid < 3) {
        float acc = bp[tid];
        for (int j = 0; j < 128; j++) acc = fmaf(qstar[j], Wp[tid * 128 + j], acc);
        out[g * 3 + tid] = acc;
    }
}

extern "C" void kernel_launch(void* const* d_in, const int* in_sizes, int n_in,
                              void* d_out, int out_size) {
    const float* feats  = (const float*)d_in[0];
    const float* W_edge = (const float*)d_in[1];
    const float* b_edge = (const float*)d_in[2];
    const float* gWih   = (const float*)d_in[3];
    const float* gWhh   = (const float*)d_in[4];
    const float* gbih   = (const float*)d_in[5];
    const float* gbhh   = (const float*)d_in[6];
    const float* wih0 = (const float*)d_in[7];
    const float* whh0 = (const float*)d_in[8];
    const float* bih0 = (const float*)d_in[9];
    const float* bhh0 = (const float*)d_in[10];
    const float* wih1 = (const float*)d_in[11];
    const float* whh1 = (const float*)d_in[12];
    const float* bih1 = (const float*)d_in[13];
    const float* bhh1 = (const float*)d_in[14];
    const float* wih2 = (const float*)d_in[15];
    const float* whh2 = (const float*)d_in[16];
    const float* bih2 = (const float*)d_in[17];
    const float* bhh2 = (const float*)d_in[18];
    const float* Wp   = (const float*)d_in[19];
    const float* bp   = (const float*)d_in[20];
    const int* src    = (const int*)d_in[21];
    const int* dst    = (const int*)d_in[22];
    const int* ety    = (const int*)d_in[23];
    float* out = (float*)d_out;

    static int inited = 0;
    if (!inited) {
        cudaFuncSetAttribute(step_kernel,
                             cudaFuncAttributeMaxDynamicSharedMemorySize, ST_SMEM);
        cudaFuncSetAttribute(set2set_kernel,
                             cudaFuncAttributeMaxDynamicSharedMemorySize, S2_SMEM);
        inited = 1;
    }

    prep_kernel<<<96, 256>>>(W_edge, gWih, gWhh);
    sort_kernel<<<NGR, 640>>>(src, dst, ety);
    for (int s = 0; s < 5; s++)
        step_kernel<<<NGR * 2, NTH, ST_SMEM>>>(feats, b_edge, gbih, gbhh, s);
    set2set_kernel<<<NGR, 320, S2_SMEM>>>(
        wih0, whh0, bih0, bhh0,
        wih1, whh1, bih1, bhh1,
        wih2, whh2, bih2, bhh2,
        Wp, bp, out);
}

// round 7
// speedup vs baseline: 3.7142x; 1.2350x over previous
#include <cuda_runtime.h>
#include <cuda_bf16.h>
#include <math.h>

// GGNN + Set2Set. R7: R6 tensor-core step kernels unchanged; Set2Set split into
// batched LSTM kernel (8 graphs/CTA, weights read 40x less) + per-graph attention
// kernel, one pair per iteration, state in global scratch.

#define NPG 200
#define EPG 3200
#define NET 6
#define NGR 320
#define NTH 448

// ---- step kernel SMEM layout (bytes) ----
#define HP_HI 0
#define HP_LO 27648
#define SP_HI 55296
#define SP_LO 69632
#define WB    83968
#define ESRCB 100352
#define OFFLB 103552
#define ST_SMEM 104768

// ---------------- global scratch ----------------
__device__ float g_hA[64000 * 64];
__device__ float g_hB[64000 * 64];
__device__ unsigned char  g_esrc[NGR * EPG];
__device__ unsigned short g_off[NGR * 1216];
__device__ unsigned int g_wfrag[12 * 4096];
// set2set state
__device__ float g_qstar[NGR * 128];
__device__ float g_lh[3 * NGR * 64];
__device__ float g_lc[3 * NGR * 64];
__device__ float g_q[NGR * 64];
// lstm weights baked: per segment [k4][gate t][4] (float4 per (k4,t))
// seg bases (floats): ih0@0(32 k4), hh0@32768(16), ih1@49152(16), hh1@65536(16),
//                     ih2@81920(16), hh2@98304(16)
__device__ float g_wtl[114688];
__device__ float g_bsum[768];

__device__ __forceinline__ float sigf(float x) { return 1.0f / (1.0f + __expf(-x)); }
__device__ __forceinline__ float tanhfast(float x) {
    x = fminf(fmaxf(x, -15.0f), 15.0f);
    float e = __expf(2.0f * x);
    return (e - 1.0f) / (e + 1.0f);
}
__device__ __forceinline__ float blo(unsigned w) { return __uint_as_float(w << 16); }
__device__ __forceinline__ float bhi(unsigned w) { return __uint_as_float(w & 0xffff0000u); }
__device__ __forceinline__ void cvtpair(float a, float b, unsigned& hi, unsigned& lo) {
    asm("cvt.rn.bf16x2.f32 %0, %1, %2;" : "=r"(hi) : "f"(b), "f"(a));
    float fa = blo(hi), fb = bhi(hi);
    asm("cvt.rn.bf16x2.f32 %0, %1, %2;" : "=r"(lo) : "f"(b - fb), "f"(a - fa));
}
__device__ __forceinline__ unsigned smem_u32(const void* p) {
    unsigned a;
    asm("{ .reg .u64 t; cvta.to.shared.u64 t, %1; cvt.u32.u64 %0, t; }" : "=r"(a) : "l"(p));
    return a;
}
__device__ __forceinline__ void ldmA(unsigned addr, unsigned r[4]) {
    asm volatile("ldmatrix.sync.aligned.m8n8.x4.shared.b16 {%0,%1,%2,%3}, [%4];"
                 : "=r"(r[0]), "=r"(r[1]), "=r"(r[2]), "=r"(r[3]) : "r"(addr));
}
__device__ __forceinline__ void mma16816(float* c, const unsigned a[4], unsigned b0, unsigned b1) {
    asm volatile("mma.sync.aligned.m16n8k16.row.col.f32.bf16.bf16.f32 "
                 "{%0,%1,%2,%3}, {%4,%5,%6,%7}, {%8,%9}, {%0,%1,%2,%3};"
                 : "+f"(c[0]), "+f"(c[1]), "+f"(c[2]), "+f"(c[3])
                 : "r"(a[0]), "r"(a[1]), "r"(a[2]), "r"(a[3]), "r"(b0), "r"(b1));
}

// ---------------- prep: bake mm B fragments ----------------
__global__ void prep_kernel(const float* __restrict__ W_edge,
                            const float* __restrict__ gWih,
                            const float* __restrict__ gWhh) {
    int i = blockIdx.x * blockDim.x + threadIdx.x;
    if (i >= 24576) return;
    int reg = i & 1, lane = (i >> 1) & 31, ks = (i >> 6) & 3;
    int ntg = (i >> 8) & 7, tile = i >> 11;
    int n = ntg * 8 + (lane >> 2);
    int k = ks * 16 + (lane & 3) * 2 + reg * 8;
    float w0, w1;
    if (tile < 6) {
        w0 = W_edge[(tile * 64 + k) * 64 + n];
        w1 = W_edge[(tile * 64 + k + 1) * 64 + n];
    } else {
        int p = tile - 6;
        const int g0s[6] = { 0, 0, 128, 128, 64, 64 };
        const float* M = (p == 0 || p == 3 || p == 4) ? gWih : gWhh;
        w0 = M[(g0s[p] + n) * 64 + k];
        w1 = M[(g0s[p] + n) * 64 + k + 1];
    }
    unsigned hw, lw;
    cvtpair(w0, w1, hw, lw);
    int base = tile * 4096 + (ntg * 4 + ks) * 64 + lane * 2 + reg;
    g_wfrag[base] = hw;
    g_wfrag[base + 2048] = lw;
}

// ---------------- prep: bake lstm transposed weights + bias sums ----------------
__global__ void prep_lstm(const float* __restrict__ wih0, const float* __restrict__ whh0,
                          const float* __restrict__ bih0, const float* __restrict__ bhh0,
                          const float* __restrict__ wih1, const float* __restrict__ whh1,
                          const float* __restrict__ bih1, const float* __restrict__ bhh1,
                          const float* __restrict__ wih2, const float* __restrict__ whh2,
                          const float* __restrict__ bih2, const float* __restrict__ bhh2) {
    int i = blockIdx.x * blockDim.x + threadIdx.x;
    if (i < 114688) {
        const int   bases[6]  = { 0, 32768, 49152, 65536, 81920, 98304 };
        const int   indims[6] = { 128, 64, 64, 64, 64, 64 };
        const float* Ws[6] = { wih0, whh0, wih1, whh1, wih2, whh2 };
        int seg = 5;
#pragma unroll
        for (int s = 0; s < 5; s++) if (i < bases[s + 1]) { seg = s; break; }
        int idx = i - bases[seg];
        int k4 = idx >> 10, r = idx & 1023, t = r >> 2, kk = r & 3;
        g_wtl[i] = Ws[seg][t * indims[seg] + k4 * 4 + kk];
    } else if (i < 115456) {
        int i2 = i - 114688;
        int l = i2 >> 8, t = i2 & 255;
        const float* bi = (l == 0) ? bih0 : (l == 1) ? bih1 : bih2;
        const float* bh = (l == 0) ? bhh0 : (l == 1) ? bhh1 : bhh2;
        g_bsum[i2] = bi[t] + bh[t];
    }
}

__global__ void init_state() {
    int i = blockIdx.x * blockDim.x + threadIdx.x;
    if (i < NGR * 128) g_qstar[i] = 0.0f;
    if (i < 3 * NGR * 64) { g_lh[i] = 0.0f; g_lc[i] = 0.0f; }
}

// ---------------- sort ----------------
__global__ __launch_bounds__(640) void sort_kernel(
    const int* __restrict__ g_src, const int* __restrict__ g_dst,
    const int* __restrict__ g_ety) {
    __shared__ int cnt[1280];
    __shared__ int csum[256];
    const int tid = threadIdx.x;
    const int g = blockIdx.x;
    const int nbase = g * NPG, ebase = g * EPG;
    for (int i = tid; i < 1280; i += 640) cnt[i] = 0;
    __syncthreads();
    for (int e = tid; e < EPG; e += 640) {
        int key = g_ety[ebase + e] * NPG + (g_dst[ebase + e] - nbase);
        atomicAdd(&cnt[key], 1);
    }
    __syncthreads();
    if (tid < 256) {
        int s = 0;
#pragma unroll
        for (int j = 0; j < 5; j++) s += cnt[tid * 5 + j];
        csum[tid] = s;
    }
    __syncthreads();
    if (tid < 32) {
        int s = 0;
#pragma unroll
        for (int j = 0; j < 8; j++) s += csum[tid * 8 + j];
        int v = s;
        for (int o = 1; o < 32; o <<= 1) {
            int u = __shfl_up_sync(0xffffffffu, v, o);
            if (tid >= o) v += u;
        }
        int run = v - s;
#pragma unroll
        for (int j = 0; j < 8; j++) {
            int c = csum[tid * 8 + j];
            csum[tid * 8 + j] = run;
            run += c;
        }
    }
    __syncthreads();
    if (tid < 256) {
        int run = csum[tid];
#pragma unroll
        for (int j = 0; j < 5; j++) {
            int idx = tid * 5 + j;
            int c = cnt[idx];
            if (idx < 1216) g_off[g * 1216 + idx] = (unsigned short)run;
            run += c;
        }
    }
    __syncthreads();
    if (tid < 256) {
        int run = csum[tid];
#pragma unroll
        for (int j = 0; j < 5; j++) {
            int idx = tid * 5 + j;
            int c = cnt[idx];
            cnt[idx] = run;
            run += c;
        }
    }
    __syncthreads();
    for (int e = tid; e < EPG; e += 640) {
        int key = g_ety[ebase + e] * NPG + (g_dst[ebase + e] - nbase);
        int pos = atomicAdd(&cnt[key], 1);
        g_esrc[g * EPG + pos] = (unsigned char)(g_src[ebase + e] - nbase);
    }
}

// ---------------- step kernel (unchanged from R6) ----------------
__global__ __launch_bounds__(NTH, 2) void step_kernel(
    const float* __restrict__ feats,
    const float* __restrict__ b_edge,
    const float* __restrict__ gbih,
    const float* __restrict__ gbhh,
    int step) {
    extern __shared__ char sm[];
    unsigned smb = smem_u32(sm);
    unsigned char* esrc = (unsigned char*)(sm + ESRCB);
    unsigned short* offl = (unsigned short*)(sm + OFFLB);

    const int tid = threadIdx.x;
    const int g = blockIdx.x >> 1;
    const int half = blockIdx.x & 1;
    const int lane = tid & 31;
    const int wid = tid >> 5;
    const int mt = wid >> 1;
    const int nh = wid & 1;
    const int lrow = mt * 16 + (lane & 15);
    const int hrow = half * 100 + lrow;
    const int lmt = lane >> 4;
    const int g8 = lane >> 2, q = lane & 3;
    const int r1l = mt * 16 + g8, r2l = r1l + 8;

    const float* hsrc = (step == 0) ? feats : ((step & 1) ? g_hA : g_hB);
    float* hdst = (step & 1) ? g_hB : g_hA;

    for (int i = tid; i < 1600; i += NTH) {
        int n = i >> 3, u = i & 7;
        const float4* src = (const float4*)(hsrc + (g * NPG + n) * 64 + u * 8);
        float4 v0 = src[0], v1 = src[1];
        unsigned hw0, lw0, hw1, lw1, hw2, lw2, hw3, lw3;
        cvtpair(v0.x, v0.y, hw0, lw0);
        cvtpair(v0.z, v0.w, hw1, lw1);
        cvtpair(v1.x, v1.y, hw2, lw2);
        cvtpair(v1.z, v1.w, hw3, lw3);
        int bo = n * 128 + (((u + n) & 7) << 4);
        *(uint4*)(sm + HP_HI + bo) = make_uint4(hw0, hw1, hw2, hw3);
        *(uint4*)(sm + HP_LO + bo) = make_uint4(lw0, lw1, lw2, lw3);
    }
    {
        const uint4* es = (const uint4*)(g_esrc + g * EPG);
        for (int i = tid; i < 200; i += NTH) ((uint4*)esrc)[i] = es[i];
        for (int j = tid; j < 606; j += NTH) {
            int t = j / 101, i2 = j % 101;
            offl[j] = g_off[g * 1216 + t * 200 + half * 100 + i2];
        }
    }

    float aC[16];
#pragma unroll
    for (int i = 0; i < 16; i++) aC[i] = 0.0f;

    for (int t = 0; t < NET; t++) {
        const uint4* ws = (const uint4*)g_wfrag + t * 1024;
        uint4 w0 = ws[tid], w1 = ws[tid + 448], w2;
        if (tid < 128) w2 = ws[tid + 896];
        __syncthreads();
        ((uint4*)(sm + WB))[tid] = w0;
        ((uint4*)(sm + WB))[tid + 448] = w1;
        if (tid < 128) ((uint4*)(sm + WB))[tid + 896] = w2;
        for (int i = tid; i < 800; i += NTH) {
            int n = i >> 3, u = i & 7;
            int b = t * 101 + n;
            int j0 = offl[b], j1 = offl[b + 1];
            float a0 = 0, a1 = 0, a2 = 0, a3 = 0, a4 = 0, a5 = 0, a6 = 0, a7 = 0;
            for (int j = j0; j < j1; j++) {
                int er = esrc[j];
                int bo = er * 128 + (((u + er) & 7) << 4);
                uint4 H = *(const uint4*)(sm + HP_HI + bo);
                uint4 L = *(const uint4*)(sm + HP_LO + bo);
                a0 += blo(H.x) + blo(L.x);  a1 += bhi(H.x) + bhi(L.x);
                a2 += blo(H.y) + blo(L.y);  a3 += bhi(H.y) + bhi(L.y);
                a4 += blo(H.z) + blo(L.z);  a5 += bhi(H.z) + bhi(L.z);
                a6 += blo(H.w) + blo(L.w);  a7 += bhi(H.w) + bhi(L.w);
            }
            unsigned hw0, lw0, hw1, lw1, hw2, lw2, hw3, lw3;
            cvtpair(a0, a1, hw0, lw0);
            cvtpair(a2, a3, hw1, lw1);
            cvtpair(a4, a5, hw2, lw2);
            cvtpair(a6, a7, hw3, lw3);
            int bo = n * 128 + (((u + n) & 7) << 4);
            *(uint4*)(sm + SP_HI + bo) = make_uint4(hw0, hw1, hw2, hw3);
            *(uint4*)(sm + SP_LO + bo) = make_uint4(lw0, lw1, lw2, lw3);
        }
        __syncthreads();
#pragma unroll
        for (int ks = 0; ks < 4; ks++) {
            int unit = 2 * ks + lmt;
            unsigned ah[4], al[4];
            ldmA(smb + SP_HI + lrow * 128 + (((unit + lrow) & 7) << 4), ah);
            ldmA(smb + SP_LO + lrow * 128 + (((unit + lrow) & 7) << 4), al);
#pragma unroll
            for (int nt = 0; nt < 4; nt++) {
                int ntg = nh * 4 + nt;
                uint2 bh = *(const uint2*)(sm + WB + (((ntg * 4 + ks) * 64) + lane * 2) * 4);
                uint2 bl = *(const uint2*)(sm + WB + ((2048 + (ntg * 4 + ks) * 64) + lane * 2) * 4);
                mma16816(aC + nt * 4, al, bh.x, bh.y);
                mma16816(aC + nt * 4, ah, bl.x, bl.y);
                mma16816(aC + nt * 4, ah, bh.x, bh.y);
            }
        }
    }
#pragma unroll
    for (int t = 0; t < NET; t++) {
        float c1 = (r1l < 100) ? (float)(offl[t * 101 + r1l + 1] - offl[t * 101 + r1l]) : 0.0f;
        float c2 = (r2l < 100) ? (float)(offl[t * 101 + r2l + 1] - offl[t * 101 + r2l]) : 0.0f;
#pragma unroll
        for (int nt = 0; nt < 4; nt++) {
            int col = nh * 32 + nt * 8 + q * 2;
            float2 b = *(const float2*)(b_edge + t * 64 + col);
            aC[nt * 4 + 0] = fmaf(c1, b.x, aC[nt * 4 + 0]);
            aC[nt * 4 + 1] = fmaf(c1, b.y, aC[nt * 4 + 1]);
            aC[nt * 4 + 2] = fmaf(c2, b.x, aC[nt * 4 + 2]);
            aC[nt * 4 + 3] = fmaf(c2, b.y, aC[nt * 4 + 3]);
        }
    }
    __syncthreads();
#pragma unroll
    for (int nt = 0; nt < 4; nt++) {
        int col = nh * 32 + nt * 8 + q * 2;
        int u = col >> 3;
        unsigned hw, lw;
        cvtpair(aC[nt * 4 + 0], aC[nt * 4 + 1], hw, lw);
        int bo1 = r1l * 128 + (((u + r1l) & 7) << 4) + q * 4;
        *(unsigned*)(sm + SP_HI + bo1) = hw;
        *(unsigned*)(sm + SP_LO + bo1) = lw;
        cvtpair(aC[nt * 4 + 2], aC[nt * 4 + 3], hw, lw);
        int bo2 = r2l * 128 + (((u + r2l) & 7) << 4) + q * 4;
        *(unsigned*)(sm + SP_HI + bo2) = hw;
        *(unsigned*)(sm + SP_LO + bo2) = lw;
    }

#define STAGEW(T) do { \
        const uint4* ws_ = (const uint4*)g_wfrag + (T) * 1024; \
        uint4 s0 = ws_[tid], s1 = ws_[tid + 448], s2; \
        if (tid < 128) s2 = ws_[tid + 896]; \
        __syncthreads(); \
        ((uint4*)(sm + WB))[tid] = s0; \
        ((uint4*)(sm + WB))[tid + 448] = s1; \
        if (tid < 128) ((uint4*)(sm + WB))[tid + 896] = s2; \
        __syncthreads(); \
    } while (0)

#define MMPASS(BASE_HI, BASE_LO, ROW, C) do { \
        _Pragma("unroll") \
        for (int ks = 0; ks < 4; ks++) { \
            int unit = 2 * ks + lmt; \
            unsigned ah[4], al[4]; \
            ldmA(smb + (BASE_HI) + (ROW) * 128 + (((unit + (ROW)) & 7) << 4), ah); \
            ldmA(smb + (BASE_LO) + (ROW) * 128 + (((unit + (ROW)) & 7) << 4), al); \
            _Pragma("unroll") \
            for (int nt = 0; nt < 4; nt++) { \
                int ntg = nh * 4 + nt; \
                uint2 bh = *(const uint2*)(sm + WB + (((ntg * 4 + ks) * 64) + lane * 2) * 4); \
                uint2 bl = *(const uint2*)(sm + WB + ((2048 + (ntg * 4 + ks) * 64) + lane * 2) * 4); \
                mma16816((C) + nt * 4, al, bh.x, bh.y); \
                mma16816((C) + nt * 4, ah, bl.x, bl.y); \
                mma16816((C) + nt * 4, ah, bh.x, bh.y); \
            } \
        } \
    } while (0)

    float C[16], rg[16];
#pragma unroll
    for (int i = 0; i < 16; i++) C[i] = 0.0f;
    STAGEW(6);  MMPASS(SP_HI, SP_LO, lrow, C);
    STAGEW(7);  MMPASS(HP_HI, HP_LO, hrow, C);
#pragma unroll
    for (int nt = 0; nt < 4; nt++) {
        int col = nh * 32 + nt * 8 + q * 2;
        float2 bi = *(const float2*)(gbih + col);
        float2 bh = *(const float2*)(gbhh + col);
        rg[nt * 4 + 0] = sigf(C[nt * 4 + 0] + bi.x + bh.x);
        rg[nt * 4 + 1] = sigf(C[nt * 4 + 1] + bi.y + bh.y);
        rg[nt * 4 + 2] = sigf(C[nt * 4 + 2] + bi.x + bh.x);
        rg[nt * 4 + 3] = sigf(C[nt * 4 + 3] + bi.y + bh.y);
    }
#pragma unroll
    for (int i = 0; i < 16; i++) C[i] = 0.0f;
    STAGEW(8);  MMPASS(HP_HI, HP_LO, hrow, C);
#pragma unroll
    for (int nt = 0; nt < 4; nt++) {
        int col = nh * 32 + nt * 8 + q * 2;
        float2 bh = *(const float2*)(gbhh + 128 + col);
        rg[nt * 4 + 0] *= (C[nt * 4 + 0] + bh.x);
        rg[nt * 4 + 1] *= (C[nt * 4 + 1] + bh.y);
        rg[nt * 4 + 2] *= (C[nt * 4 + 2] + bh.x);
        rg[nt * 4 + 3] *= (C[nt * 4 + 3] + bh.y);
    }
#pragma unroll
    for (int i = 0; i < 16; i++) C[i] = 0.0f;
    STAGEW(9);  MMPASS(SP_HI, SP_LO, lrow, C);
#pragma unroll
    for (int nt = 0; nt < 4; nt++) {
        int col = nh * 32 + nt * 8 + q * 2;
        float2 bi = *(const float2*)(gbih + 128 + col);
        rg[nt * 4 + 0] = tanhfast(C[nt * 4 + 0] + bi.x + rg[nt * 4 + 0]);
        rg[nt * 4 + 1] = tanhfast(C[nt * 4 + 1] + bi.y + rg[nt * 4 + 1]);
        rg[nt * 4 + 2] = tanhfast(C[nt * 4 + 2] + bi.x + rg[nt * 4 + 2]);
        rg[nt * 4 + 3] = tanhfast(C[nt * 4 + 3] + bi.y + rg[nt * 4 + 3]);
    }
#pragma unroll
    for (int i = 0; i < 16; i++) C[i] = 0.0f;
    STAGEW(10); MMPASS(SP_HI, SP_LO, lrow, C);
    STAGEW(11); MMPASS(HP_HI, HP_LO, hrow, C);
#pragma unroll
    for (int nt = 0; nt < 4; nt++) {
        int col = nh * 32 + nt * 8 + q * 2;
        int u = col >> 3;
        float2 bi = *(const float2*)(gbih + 64 + col);
        float2 bh2 = *(const float2*)(gbhh + 64 + col);
        if (r1l < 100) {
            int gr = half * 100 + r1l;
            int bo = gr * 128 + (((u + gr) & 7) << 4) + q * 4;
            unsigned hw = *(const unsigned*)(sm + HP_HI + bo);
            unsigned lw = *(const unsigned*)(sm + HP_LO + bo);
            float h0 = blo(hw) + blo(lw), h1 = bhi(hw) + bhi(lw);
            float z0 = sigf(C[nt * 4 + 0] + bi.x + bh2.x);
            float z1 = sigf(C[nt * 4 + 1] + bi.y + bh2.y);
            float n0 = rg[nt * 4 + 0], n1 = rg[nt * 4 + 1];
            float2 o;
            o.x = fmaf(z0, h0 - n0, n0);
            o.y = fmaf(z1, h1 - n1, n1);
            *(float2*)(hdst + (g * NPG + gr) * 64 + col) = o;
        }
        if (r2l < 100) {
            int gr = half * 100 + r2l;
            int bo = gr * 128 + (((u + gr) & 7) << 4) + q * 4;
            unsigned hw = *(const unsigned*)(sm + HP_HI + bo);
            unsigned lw = *(const unsigned*)(sm + HP_LO + bo);
            float h0 = blo(hw) + blo(lw), h1 = bhi(hw) + bhi(lw);
            float z0 = sigf(C[nt * 4 + 2] + bi.x + bh2.x);
            float z1 = sigf(C[nt * 4 + 3] + bi.y + bh2.y);
            float n0 = rg[nt * 4 + 2], n1 = rg[nt * 4 + 3];
            float2 o;
            o.x = fmaf(z0, h0 - n0, n0);
            o.y = fmaf(z1, h1 - n1, n1);
            *(float2*)(hdst + (g * NPG + gr) * 64 + col) = o;
        }
    }
#undef STAGEW
#undef MMPASS
}

// ---------------- batched LSTM: 40 CTAs x 8 graphs ----------------
__global__ __launch_bounds__(256) void lstm_kernel() {
    __shared__ float xs[8][128];
    __shared__ float hp[8][64];
    __shared__ float cp[8][64];
    __shared__ float gs[8][256];
    const int tid = threadIdx.x;
    const int g0 = blockIdx.x * 8;
    for (int i = tid; i < 1024; i += 256) {
        int j = i >> 7, k = i & 127;
        xs[j][k] = g_qstar[(g0 + j) * 128 + k];
    }
    const int ihbase[3] = { 0, 49152, 81920 };
    const int hhbase[3] = { 32768, 65536, 98304 };
    for (int l = 0; l < 3; l++) {
        int nk4 = l ? 16 : 32;
        for (int i = tid; i < 512; i += 256) {
            int j = i >> 6, d = i & 63;
            hp[j][d] = g_lh[l * NGR * 64 + (g0 + j) * 64 + d];
            cp[j][d] = g_lc[l * NGR * 64 + (g0 + j) * 64 + d];
        }
        __syncthreads();
        float acc[8];
        float bs = g_bsum[l * 256 + tid];
#pragma unroll
        for (int j = 0; j < 8; j++) acc[j] = bs;
        const float4* Wi = (const float4*)(g_wtl + ihbase[l]) + tid;
        for (int k4 = 0; k4 < nk4; k4++) {
            float4 w = Wi[k4 * 256];
#pragma unroll
            for (int j = 0; j < 8; j++) {
                float4 xv = *(const float4*)&xs[j][k4 * 4];
                acc[j] = fmaf(w.x, xv.x, fmaf(w.y, xv.y, fmaf(w.z, xv.z, fmaf(w.w, xv.w, acc[j]))));
            }
        }
        const float4* Wh = (const float4*)(g_wtl + hhbase[l]) + tid;
        for (int k4 = 0; k4 < 16; k4++) {
            float4 w = Wh[k4 * 256];
#pragma unroll
            for (int j = 0; j < 8; j++) {
                float4 hv = *(const float4*)&hp[j][k4 * 4];
                acc[j] = fmaf(w.x, hv.x, fmaf(w.y, hv.y, fmaf(w.z, hv.z, fmaf(w.w, hv.w, acc[j]))));
            }
        }
#pragma unroll
        for (int j = 0; j < 8; j++) gs[j][tid] = acc[j];
        __syncthreads();
        for (int i = tid; i < 512; i += 256) {
            int j = i >> 6, d = i & 63;
            float c = sigf(gs[j][64 + d]) * cp[j][d] + sigf(gs[j][d]) * tanhfast(gs[j][128 + d]);
            float hn = sigf(gs[j][192 + d]) * tanhfast(c);
            g_lc[l * NGR * 64 + (g0 + j) * 64 + d] = c;
            g_lh[l * NGR * 64 + (g0 + j) * 64 + d] = hn;
            xs[j][d] = hn;
            if (l == 2) g_q[(g0 + j) * 64 + d] = hn;
        }
        __syncthreads();
    }
}

// ---------------- attention: one CTA per graph ----------------
#define AP 68
#define ATT_SMEM ((13600 + 64 + 64 + 200 + 256) * 4)

__global__ __launch_bounds__(256, 2) void attn_kernel(
    const float* __restrict__ Wp, const float* __restrict__ bp,
    float* __restrict__ out, int last) {
    extern __shared__ float smf[];
    float* hs    = smf;                 // 200*68
    float* qv    = smf + 13600;         // 64
    float* red   = smf + 13664;         // 64
    float* alpha = smf + 13728;         // 200
    float* part  = smf + 13928;         // 256
    const int tid = threadIdx.x;
    const int g = blockIdx.x;
    const int lane = tid & 31;
    const int wrp = tid >> 5;           // 0..7

    for (int i = tid; i < 3200; i += 256) {
        int n = i >> 4, c4 = i & 15;
        *(float4*)&hs[n * AP + c4 * 4] = *(const float4*)(g_hA + (g * NPG + n) * 64 + c4 * 4);
    }
    if (tid < 64) qv[tid] = g_q[g * 64 + tid];
    __syncthreads();

    float e = -3.4e38f;
    if (tid < NPG) {
        float a = 0.0f;
#pragma unroll 4
        for (int c4 = 0; c4 < 16; c4++) {
            float4 hv = *(const float4*)&hs[tid * AP + c4 * 4];
            float4 q4 = *(const float4*)&qv[c4 * 4];
            a = fmaf(hv.x, q4.x, fmaf(hv.y, q4.y, fmaf(hv.z, q4.z, fmaf(hv.w, q4.w, a))));
        }
        e = a;
    }
    float m = e;
#pragma unroll
    for (int o = 16; o >= 1; o >>= 1) m = fmaxf(m, __shfl_xor_sync(0xffffffffu, m, o));
    if (lane == 0) red[wrp] = m;
    __syncthreads();
    if (tid == 0) {
        float mm = red[0];
        for (int w = 1; w < 8; w++) mm = fmaxf(mm, red[w]);
        red[32] = mm;
    }
    __syncthreads();
    float ex = (tid < NPG) ? __expf(e - red[32]) : 0.0f;
    float ss = ex;
#pragma unroll
    for (int o = 16; o >= 1; o >>= 1) ss += __shfl_xor_sync(0xffffffffu, ss, o);
    if (lane == 0) red[wrp] = ss;
    __syncthreads();
    if (tid == 0) {
        float s = 0.0f;
        for (int w = 0; w < 8; w++) s += red[w];
        red[33] = s;
    }
    __syncthreads();
    if (tid < NPG) alpha[tid] = ex / red[33];
    __syncthreads();
    {
        int d = tid & 63, grp = tid >> 6;   // 4 groups of 50 nodes
        float a = 0.0f;
        int nlo = grp * 50;
        for (int n = nlo; n < nlo + 50; n++)
            a = fmaf(hs[n * AP + d], alpha[n], a);
        part[tid] = a;
    }
    __syncthreads();
    if (tid < 64) {
        float ro = part[tid] + part[64 + tid] + part[128 + tid] + part[192 + tid];
        g_qstar[g * 128 + tid] = qv[tid];
        g_qstar[g * 128 + 64 + tid] = ro;
    }
    if (last) {
        __syncthreads();
        if (tid < 3) {
            float a = bp[tid];
            for (int j = 0; j < 128; j++)
                a = fmaf(g_qstar[g * 128 + j], Wp[tid * 128 + j], a);
            out[g * 3 + tid] = a;
        }
    }
}

extern "C" void kernel_launch(void* const* d_in, const int* in_sizes, int n_in,
                              void* d_out, int out_size) {
    const float* feats  = (const float*)d_in[0];
    const float* W_edge = (const float*)d_in[1];
    const float* b_edge = (const float*)d_in[2];
    const float* gWih   = (const float*)d_in[3];
    const float* gWhh   = (const float*)d_in[4];
    const float* gbih   = (const float*)d_in[5];
    const float* gbhh   = (const float*)d_in[6];
    const float* wih0 = (const float*)d_in[7];
    const float* whh0 = (const float*)d_in[8];
    const float* bih0 = (const float*)d_in[9];
    const float* bhh0 = (const float*)d_in[10];
    const float* wih1 = (const float*)d_in[11];
    const float* whh1 = (const float*)d_in[12];
    const float* bih1 = (const float*)d_in[13];
    const float* bhh1 = (const float*)d_in[14];
    const float* wih2 = (const float*)d_in[15];
    const float* whh2 = (const float*)d_in[16];
    const float* bih2 = (const float*)d_in[17];
    const float* bhh2 = (const float*)d_in[18];
    const float* Wp   = (const float*)d_in[19];
    const float* bp   = (const float*)d_in[20];
    const int* src    = (const int*)d_in[21];
    const int* dst    = (const int*)d_in[22];
    const int* ety    = (const int*)d_in[23];
    float* out = (float*)d_out;

    static int inited = 0;
    if (!inited) {
        cudaFuncSetAttribute(step_kernel,
                             cudaFuncAttributeMaxDynamicSharedMemorySize, ST_SMEM);
        cudaFuncSetAttribute(attn_kernel,
                             cudaFuncAttributeMaxDynamicSharedMemorySize, ATT_SMEM);
        inited = 1;
    }

    prep_kernel<<<96, 256>>>(W_edge, gWih, gWhh);
    prep_lstm<<<452, 256>>>(wih0, whh0, bih0, bhh0,
                            wih1, whh1, bih1, bhh1,
                            wih2, whh2, bih2, bhh2);
    sort_kernel<<<NGR, 640>>>(src, dst, ety);
    init_state<<<240, 256>>>();
    for (int s = 0; s < 5; s++)
        step_kernel<<<NGR * 2, NTH, ST_SMEM>>>(feats, b_edge, gbih, gbhh, s);
    for (int it = 0; it < 6; it++) {
        lstm_kernel<<<40, 256>>>();
        attn_kernel<<<NGR, 256, ATT_SMEM>>>(Wp, bp, out, it == 5 ? 1 : 0);
    }
}

// round 9
// speedup vs baseline: 3.8727x; 1.0427x over previous
#include <cuda_runtime.h>
#include <cuda_bf16.h>
#include <math.h>

// GGNN + Set2Set. R8: step kernel gathers over fp32 h (no bf16 decode),
// own-half bf16-pair h built via SMEM phase overlay, packed B fragments
// (1 LDS.128/mma-group), init_state folded into prep_lstm.

#define NPG 200
#define EPG 3200
#define NET 6
#define NGR 320
#define NTH 448

// ---- step kernel SMEM layout (bytes) ----
#define H_F32 0              // 200 rows x 288B (fp32 h, bank-rotated pitch)
#define SP_HI 57600          // 112 rows x 128B (s/a hi)
#define SP_LO 71936
#define WB    86272          // 16384B staged B fragments
#define ESRCB 102656         // 3200B
#define OFFLB 105856         // 606 u16 (pad)
#define ST_SMEM 107072
// HP pair (own half, built in phase B) overlays H_F32:
//   half==0 -> base 28928 (reads rows 0..99 at 0..28800)
//   half==1 -> base 0     (reads rows 100..199 at 28800..57600)

// ---------------- global scratch ----------------
__device__ float g_hA[64000 * 64];
__device__ float g_hB[64000 * 64];
__device__ unsigned char  g_esrc[NGR * EPG];
__device__ unsigned short g_off[NGR * 1216];
// B fragments: [tile][ (ntg*4+ks)*32 + lane ] = uint4 {hi_r0, hi_r1, lo_r0, lo_r1}
__device__ unsigned int g_wfrag[12 * 4096];
// set2set state
__device__ float g_qstar[NGR * 128];
__device__ float g_lh[3 * NGR * 64];
__device__ float g_lc[3 * NGR * 64];
__device__ float g_q[NGR * 64];
__device__ float g_wtl[114688];
__device__ float g_bsum[768];

__device__ __forceinline__ float sigf(float x) { return 1.0f / (1.0f + __expf(-x)); }
__device__ __forceinline__ float tanhfast(float x) {
    x = fminf(fmaxf(x, -15.0f), 15.0f);
    float e = __expf(2.0f * x);
    return (e - 1.0f) / (e + 1.0f);
}
__device__ __forceinline__ float blo(unsigned w) { return __uint_as_float(w << 16); }
__device__ __forceinline__ float bhi(unsigned w) { return __uint_as_float(w & 0xffff0000u); }
__device__ __forceinline__ void cvtpair(float a, float b, unsigned& hi, unsigned& lo) {
    asm("cvt.rn.bf16x2.f32 %0, %1, %2;" : "=r"(hi) : "f"(b), "f"(a));
    float fa = blo(hi), fb = bhi(hi);
    asm("cvt.rn.bf16x2.f32 %0, %1, %2;" : "=r"(lo) : "f"(b - fb), "f"(a - fa));
}
__device__ __forceinline__ unsigned smem_u32(const void* p) {
    unsigned a;
    asm("{ .reg .u64 t; cvta.to.shared.u64 t, %1; cvt.u32.u64 %0, t; }" : "=r"(a) : "l"(p));
    return a;
}
__device__ __forceinline__ void ldmA(unsigned addr, unsigned r[4]) {
    asm volatile("ldmatrix.sync.aligned.m8n8.x4.shared.b16 {%0,%1,%2,%3}, [%4];"
                 : "=r"(r[0]), "=r"(r[1]), "=r"(r[2]), "=r"(r[3]) : "r"(addr));
}
__device__ __forceinline__ void mma16816(float* c, const unsigned a[4], unsigned b0, unsigned b1) {
    asm volatile("mma.sync.aligned.m16n8k16.row.col.f32.bf16.bf16.f32 "
                 "{%0,%1,%2,%3}, {%4,%5,%6,%7}, {%8,%9}, {%0,%1,%2,%3};"
                 : "+f"(c[0]), "+f"(c[1]), "+f"(c[2]), "+f"(c[3])
                 : "r"(a[0]), "r"(a[1]), "r"(a[2]), "r"(a[3]), "r"(b0), "r"(b1));
}

// ---------------- prep: bake packed B fragments ----------------
__global__ void prep_kernel(const float* __restrict__ W_edge,
                            const float* __restrict__ gWih,
                            const float* __restrict__ gWhh) {
    int i = blockIdx.x * blockDim.x + threadIdx.x;
    if (i >= 49152) return;
    int word = i & 3, lane = (i >> 2) & 31, ks = (i >> 7) & 3;
    int ntg = (i >> 9) & 7, tile = i >> 12;
    int reg = word & 1, split = word >> 1;
    int n = ntg * 8 + (lane >> 2);
    int k = ks * 16 + (lane & 3) * 2 + reg * 8;
    float w0, w1;
    if (tile < 6) {
        w0 = W_edge[(tile * 64 + k) * 64 + n];
        w1 = W_edge[(tile * 64 + k + 1) * 64 + n];
    } else {
        int p = tile - 6;
        const int g0s[6] = { 0, 0, 128, 128, 64, 64 };
        const float* M = (p == 0 || p == 3 || p == 4) ? gWih : gWhh;
        w0 = M[(g0s[p] + n) * 64 + k];
        w1 = M[(g0s[p] + n) * 64 + k + 1];
    }
    unsigned hw, lw;
    cvtpair(w0, w1, hw, lw);
    g_wfrag[tile * 4096 + (((ntg * 4 + ks) * 32 + lane) << 2) + word] = split ? lw : hw;
}

// ---------------- prep: lstm weights + bias sums + state init ----------------
__global__ void prep_lstm(const float* __restrict__ wih0, const float* __restrict__ whh0,
                          const float* __restrict__ bih0, const float* __restrict__ bhh0,
                          const float* __restrict__ wih1, const float* __restrict__ whh1,
                          const float* __restrict__ bih1, const float* __restrict__ bhh1,
                          const float* __restrict__ wih2, const float* __restrict__ whh2,
                          const float* __restrict__ bih2, const float* __restrict__ bhh2) {
    int i = blockIdx.x * blockDim.x + threadIdx.x;
    if (i < 114688) {
        const int   bases[6]  = { 0, 32768, 49152, 65536, 81920, 98304 };
        const int   indims[6] = { 128, 64, 64, 64, 64, 64 };
        const float* Ws[6] = { wih0, whh0, wih1, whh1, wih2, whh2 };
        int seg = 5;
#pragma unroll
        for (int s = 0; s < 5; s++) if (i < bases[s + 1]) { seg = s; break; }
        int idx = i - bases[seg];
        int k4 = idx >> 10, r = idx & 1023, t = r >> 2, kk = r & 3;
        g_wtl[i] = Ws[seg][t * indims[seg] + k4 * 4 + kk];
    } else if (i < 115456) {
        int i2 = i - 114688;
        int l = i2 >> 8, t = i2 & 255;
        const float* bi = (l == 0) ? bih0 : (l == 1) ? bih1 : bih2;
        const float* bh = (l == 0) ? bhh0 : (l == 1) ? bhh1 : bhh2;
        g_bsum[i2] = bi[t] + bh[t];
    }
    if (i < NGR * 128) g_qstar[i] = 0.0f;
    if (i < 3 * NGR * 64) { g_lh[i] = 0.0f; g_lc[i] = 0.0f; }
}

// ---------------- sort ----------------
__global__ __launch_bounds__(640) void sort_kernel(
    const int* __restrict__ g_src, const int* __restrict__ g_dst,
    const int* __restrict__ g_ety) {
    __shared__ int cnt[1280];
    __shared__ int csum[256];
    const int tid = threadIdx.x;
    const int g = blockIdx.x;
    const int nbase = g * NPG, ebase = g * EPG;
    for (int i = tid; i < 1280; i += 640) cnt[i] = 0;
    __syncthreads();
    for (int e = tid; e < EPG; e += 640) {
        int key = g_ety[ebase + e] * NPG + (g_dst[ebase + e] - nbase);
        atomicAdd(&cnt[key], 1);
    }
    __syncthreads();
    if (tid < 256) {
        int s = 0;
#pragma unroll
        for (int j = 0; j < 5; j++) s += cnt[tid * 5 + j];
        csum[tid] = s;
    }
    __syncthreads();
    if (tid < 32) {
        int s = 0;
#pragma unroll
        for (int j = 0; j < 8; j++) s += csum[tid * 8 + j];
        int v = s;
        for (int o = 1; o < 32; o <<= 1) {
            int u = __shfl_up_sync(0xffffffffu, v, o);
            if (tid >= o) v += u;
        }
        int run = v - s;
#pragma unroll
        for (int j = 0; j < 8; j++) {
            int c = csum[tid * 8 + j];
            csum[tid * 8 + j] = run;
            run += c;
        }
    }
    __syncthreads();
    if (tid < 256) {
        int run = csum[tid];
#pragma unroll
        for (int j = 0; j < 5; j++) {
            int idx = tid * 5 + j;
            int c = cnt[idx];
            if (idx < 1216) g_off[g * 1216 + idx] = (unsigned short)run;
            run += c;
        }
    }
    __syncthreads();
    if (tid < 256) {
        int run = csum[tid];
#pragma unroll
        for (int j = 0; j < 5; j++) {
            int idx = tid * 5 + j;
            int c = cnt[idx];
            cnt[idx] = run;
            run += c;
        }
    }
    __syncthreads();
    for (int e = tid; e < EPG; e += 640) {
        int key = g_ety[ebase + e] * NPG + (g_dst[ebase + e] - nbase);
        int pos = atomicAdd(&cnt[key], 1);
        g_esrc[g * EPG + pos] = (unsigned char)(g_src[ebase + e] - nbase);
    }
}

// ---------------- step kernel ----------------
__global__ __launch_bounds__(NTH, 2) void step_kernel(
    const float* __restrict__ feats,
    const float* __restrict__ b_edge,
    const float* __restrict__ gbih,
    const float* __restrict__ gbhh,
    int step) {
    extern __shared__ char sm[];
    unsigned smb = smem_u32(sm);
    unsigned char* esrc = (unsigned char*)(sm + ESRCB);
    unsigned short* offl = (unsigned short*)(sm + OFFLB);

    const int tid = threadIdx.x;
    const int g = blockIdx.x >> 1;
    const int half = blockIdx.x & 1;
    const int lane = tid & 31;
    const int wid = tid >> 5;
    const int mt = wid >> 1;
    const int nh = wid & 1;
    const int lrow = mt * 16 + (lane & 15);
    const int lmt = lane >> 4;
    const int g8 = lane >> 2, q = lane & 3;
    const int r1l = mt * 16 + g8, r2l = r1l + 8;
    const int hpb = half ? 0 : 28928;      // HP pair base (overlay on H_F32)

    const float* hsrc = (step == 0) ? feats : ((step & 1) ? g_hA : g_hB);
    float* hdst = (step & 1) ? g_hB : g_hA;

    // ---- load: full-graph h fp32 (pitch 288B), esrc, own-half offsets ----
    for (int i = tid; i < 3200; i += NTH) {
        int n = i >> 4, c4 = i & 15;
        *(float4*)(sm + H_F32 + n * 288 + c4 * 16) =
            *(const float4*)(hsrc + (g * NPG + n) * 64 + c4 * 4);
    }
    {
        const uint4* es = (const uint4*)(g_esrc + g * EPG);
        for (int i = tid; i < 200; i += NTH) ((uint4*)esrc)[i] = es[i];
        for (int j = tid; j < 606; j += NTH) {
            int t = j / 101, i2 = j % 101;
            offl[j] = g_off[g * 1216 + t * 200 + half * 100 + i2];
        }
    }

    // ---- etype passes: aC = sum_t (S_t @ W_t) ----
    float aC[16];
#pragma unroll
    for (int i = 0; i < 16; i++) aC[i] = 0.0f;

    for (int t = 0; t < NET; t++) {
        const uint4* ws = (const uint4*)g_wfrag + t * 1024;
        uint4 w0 = ws[tid], w1 = ws[tid + 448], w2;
        if (tid < 128) w2 = ws[tid + 896];
        __syncthreads();
        ((uint4*)(sm + WB))[tid] = w0;
        ((uint4*)(sm + WB))[tid + 448] = w1;
        if (tid < 128) ((uint4*)(sm + WB))[tid + 896] = w2;
        // fp32 gather -> s bf16 pair (own half)
        for (int i = tid; i < 800; i += NTH) {
            int n = i >> 3, u = i & 7;
            int b = t * 101 + n;
            int j0 = offl[b], j1 = offl[b + 1];
            float4 s0 = make_float4(0.f, 0.f, 0.f, 0.f);
            float4 s1 = make_float4(0.f, 0.f, 0.f, 0.f);
            for (int j = j0; j < j1; j++) {
                const float4* h4 = (const float4*)(sm + H_F32 + (int)esrc[j] * 288 + u * 32);
                float4 v0 = h4[0], v1 = h4[1];
                s0.x += v0.x; s0.y += v0.y; s0.z += v0.z; s0.w += v0.w;
                s1.x += v1.x; s1.y += v1.y; s1.z += v1.z; s1.w += v1.w;
            }
            unsigned hw0, lw0, hw1, lw1, hw2, lw2, hw3, lw3;
            cvtpair(s0.x, s0.y, hw0, lw0);
            cvtpair(s0.z, s0.w, hw1, lw1);
            cvtpair(s1.x, s1.y, hw2, lw2);
            cvtpair(s1.z, s1.w, hw3, lw3);
            int bo = n * 128 + (((u + n) & 7) << 4);
            *(uint4*)(sm + SP_HI + bo) = make_uint4(hw0, hw1, hw2, hw3);
            *(uint4*)(sm + SP_LO + bo) = make_uint4(lw0, lw1, lw2, lw3);
        }
        __syncthreads();
#pragma unroll
        for (int ks = 0; ks < 4; ks++) {
            int unit = 2 * ks + lmt;
            unsigned ah[4], al[4];
            ldmA(smb + SP_HI + lrow * 128 + (((unit + lrow) & 7) << 4), ah);
            ldmA(smb + SP_LO + lrow * 128 + (((unit + lrow) & 7) << 4), al);
#pragma unroll
            for (int nt = 0; nt < 4; nt++) {
                int ntg = nh * 4 + nt;
                uint4 bb = *(const uint4*)(sm + WB + (((ntg * 4 + ks) * 32 + lane) << 4));
                mma16816(aC + nt * 4, al, bb.x, bb.y);
                mma16816(aC + nt * 4, ah, bb.z, bb.w);
                mma16816(aC + nt * 4, ah, bb.x, bb.y);
            }
        }
    }
    // bias: aC += cnt_t(row) * b_edge[t][col]
#pragma unroll
    for (int t = 0; t < NET; t++) {
        float c1 = (r1l < 100) ? (float)(offl[t * 101 + r1l + 1] - offl[t * 101 + r1l]) : 0.0f;
        float c2 = (r2l < 100) ? (float)(offl[t * 101 + r2l + 1] - offl[t * 101 + r2l]) : 0.0f;
#pragma unroll
        for (int nt = 0; nt < 4; nt++) {
            int col = nh * 32 + nt * 8 + q * 2;
            float2 b = *(const float2*)(b_edge + t * 64 + col);
            aC[nt * 4 + 0] = fmaf(c1, b.x, aC[nt * 4 + 0]);
            aC[nt * 4 + 1] = fmaf(c1, b.y, aC[nt * 4 + 1]);
            aC[nt * 4 + 2] = fmaf(c2, b.x, aC[nt * 4 + 2]);
            aC[nt * 4 + 3] = fmaf(c2, b.y, aC[nt * 4 + 3]);
        }
    }
    __syncthreads();   // all mma reads of SP + all gathers of H_F32 done
    // write a -> SP bf16 pair
#pragma unroll
    for (int nt = 0; nt < 4; nt++) {
        int col = nh * 32 + nt * 8 + q * 2;
        int u = col >> 3;
        unsigned hw, lw;
        cvtpair(aC[nt * 4 + 0], aC[nt * 4 + 1], hw, lw);
        int bo1 = r1l * 128 + (((u + r1l) & 7) << 4) + q * 4;
        *(unsigned*)(sm + SP_HI + bo1) = hw;
        *(unsigned*)(sm + SP_LO + bo1) = lw;
        cvtpair(aC[nt * 4 + 2], aC[nt * 4 + 3], hw, lw);
        int bo2 = r2l * 128 + (((u + r2l) & 7) << 4) + q * 4;
        *(unsigned*)(sm + SP_HI + bo2) = hw;
        *(unsigned*)(sm + SP_LO + bo2) = lw;
    }
    // build HP pair (own half) from H_F32 into disjoint overlay region
    for (int i = tid; i < 800; i += NTH) {
        int r = i >> 3, u = i & 7;
        const float4* h4 = (const float4*)(sm + H_F32 + (half * 100 + r) * 288 + u * 32);
        float4 v0 = h4[0], v1 = h4[1];
        unsigned hw0, lw0, hw1, lw1, hw2, lw2, hw3, lw3;
        cvtpair(v0.x, v0.y, hw0, lw0);
        cvtpair(v0.z, v0.w, hw1, lw1);
        cvtpair(v1.x, v1.y, hw2, lw2);
        cvtpair(v1.z, v1.w, hw3, lw3);
        int bo = r * 128 + (((u + r) & 7) << 4);
        *(uint4*)(sm + hpb + bo) = make_uint4(hw0, hw1, hw2, hw3);
        *(uint4*)(sm + hpb + 14336 + bo) = make_uint4(lw0, lw1, lw2, lw3);
    }

    // ---- GRU ----
#define STAGEW(T) do { \
        const uint4* ws_ = (const uint4*)g_wfrag + (T) * 1024; \
        uint4 s0 = ws_[tid], s1 = ws_[tid + 448], s2; \
        if (tid < 128) s2 = ws_[tid + 896]; \
        __syncthreads(); \
        ((uint4*)(sm + WB))[tid] = s0; \
        ((uint4*)(sm + WB))[tid + 448] = s1; \
        if (tid < 128) ((uint4*)(sm + WB))[tid + 896] = s2; \
        __syncthreads(); \
    } while (0)

#define MMPASS(BASE_HI, BASE_LO, ROW, C) do { \
        _Pragma("unroll") \
        for (int ks = 0; ks < 4; ks++) { \
            int unit = 2 * ks + lmt; \
            unsigned ah[4], al[4]; \
            ldmA(smb + (BASE_HI) + (ROW) * 128 + (((unit + (ROW)) & 7) << 4), ah); \
            ldmA(smb + (BASE_LO) + (ROW) * 128 + (((unit + (ROW)) & 7) << 4), al); \
            _Pragma("unroll") \
            for (int nt = 0; nt < 4; nt++) { \
                int ntg = nh * 4 + nt; \
                uint4 bb = *(const uint4*)(sm + WB + (((ntg * 4 + ks) * 32 + lane) << 4)); \
                mma16816((C) + nt * 4, al, bb.x, bb.y); \
                mma16816((C) + nt * 4, ah, bb.z, bb.w); \
                mma16816((C) + nt * 4, ah, bb.x, bb.y); \
            } \
        } \
    } while (0)

    float C[16], rg[16];
    // r = sigmoid(a@Wih_r + h@Whh_r + b)
#pragma unroll
    for (int i = 0; i < 16; i++) C[i] = 0.0f;
    STAGEW(6);  MMPASS(SP_HI, SP_LO, lrow, C);
    STAGEW(7);  MMPASS(hpb, hpb + 14336, lrow, C);
#pragma unroll
    for (int nt = 0; nt < 4; nt++) {
        int col = nh * 32 + nt * 8 + q * 2;
        float2 bi = *(const float2*)(gbih + col);
        float2 bh = *(const float2*)(gbhh + col);
        rg[nt * 4 + 0] = sigf(C[nt * 4 + 0] + bi.x + bh.x);
        rg[nt * 4 + 1] = sigf(C[nt * 4 + 1] + bi.y + bh.y);
        rg[nt * 4 + 2] = sigf(C[nt * 4 + 2] + bi.x + bh.x);
        rg[nt * 4 + 3] = sigf(C[nt * 4 + 3] + bi.y + bh.y);
    }
    // t = r * (h@Whh_n + bhh_n)
#pragma unroll
    for (int i = 0; i < 16; i++) C[i] = 0.0f;
    STAGEW(8);  MMPASS(hpb, hpb + 14336, lrow, C);
#pragma unroll
    for (int nt = 0; nt < 4; nt++) {
        int col = nh * 32 + nt * 8 + q * 2;
        float2 bh = *(const float2*)(gbhh + 128 + col);
        rg[nt * 4 + 0] *= (C[nt * 4 + 0] + bh.x);
        rg[nt * 4 + 1] *= (C[nt * 4 + 1] + bh.y);
        rg[nt * 4 + 2] *= (C[nt * 4 + 2] + bh.x);
        rg[nt * 4 + 3] *= (C[nt * 4 + 3] + bh.y);
    }
    // n = tanh(a@Wih_n + bih_n + t)
#pragma unroll
    for (int i = 0; i < 16; i++) C[i] = 0.0f;
    STAGEW(9);  MMPASS(SP_HI, SP_LO, lrow, C);
#pragma unroll
    for (int nt = 0; nt < 4; nt++) {
        int col = nh * 32 + nt * 8 + q * 2;
        float2 bi = *(const float2*)(gbih + 128 + col);
        rg[nt * 4 + 0] = tanhfast(C[nt * 4 + 0] + bi.x + rg[nt * 4 + 0]);
        rg[nt * 4 + 1] = tanhfast(C[nt * 4 + 1] + bi.y + rg[nt * 4 + 1]);
        rg[nt * 4 + 2] = tanhfast(C[nt * 4 + 2] + bi.x + rg[nt * 4 + 2]);
        rg[nt * 4 + 3] = tanhfast(C[nt * 4 + 3] + bi.y + rg[nt * 4 + 3]);
    }
    // z = sigmoid(a@Wih_z + h@Whh_z + b); h' = n + z*(h - n)
#pragma unroll
    for (int i = 0; i < 16; i++) C[i] = 0.0f;
    STAGEW(10); MMPASS(SP_HI, SP_LO, lrow, C);
    STAGEW(11); MMPASS(hpb, hpb + 14336, lrow, C);
#pragma unroll
    for (int nt = 0; nt < 4; nt++) {
        int col = nh * 32 + nt * 8 + q * 2;
        int u = col >> 3;
        float2 bi = *(const float2*)(gbih + 64 + col);
        float2 bh2 = *(const float2*)(gbhh + 64 + col);
        if (r1l < 100) {
            int bo = r1l * 128 + (((u + r1l) & 7) << 4) + q * 4;
            unsigned hw = *(const unsigned*)(sm + hpb + bo);
            unsigned lw = *(const unsigned*)(sm + hpb + 14336 + bo);
            float h0 = blo(hw) + blo(lw), h1 = bhi(hw) + bhi(lw);
            float z0 = sigf(C[nt * 4 + 0] + bi.x + bh2.x);
            float z1 = sigf(C[nt * 4 + 1] + bi.y + bh2.y);
            float n0 = rg[nt * 4 + 0], n1 = rg[nt * 4 + 1];
            float2 o;
            o.x = fmaf(z0, h0 - n0, n0);
            o.y = fmaf(z1, h1 - n1, n1);
            *(float2*)(hdst + (g * NPG + half * 100 + r1l) * 64 + col) = o;
        }
        if (r2l < 100) {
            int bo = r2l * 128 + (((u + r2l) & 7) << 4) + q * 4;
            unsigned hw = *(const unsigned*)(sm + hpb + bo);
            unsigned lw = *(const unsigned*)(sm + hpb + 14336 + bo);
            float h0 = blo(hw) + blo(lw), h1 = bhi(hw) + bhi(lw);
            float z0 = sigf(C[nt * 4 + 2] + bi.x + bh2.x);
            float z1 = sigf(C[nt * 4 + 3] + bi.y + bh2.y);
            float n0 = rg[nt * 4 + 2], n1 = rg[nt * 4 + 3];
            float2 o;
            o.x = fmaf(z0, h0 - n0, n0);
            o.y = fmaf(z1, h1 - n1, n1);
            *(float2*)(hdst + (g * NPG + half * 100 + r2l) * 64 + col) = o;
        }
    }
#undef STAGEW
#undef MMPASS
}

// ---------------- batched LSTM: 40 CTAs x 8 graphs ----------------
__global__ __launch_bounds__(256) void lstm_kernel() {
    __shared__ float xs[8][128];
    __shared__ float hp[8][64];
    __shared__ float cp[8][64];
    __shared__ float gs[8][256];
    const int tid = threadIdx.x;
    const int g0 = blockIdx.x * 8;
    for (int i = tid; i < 1024; i += 256) {
        int j = i >> 7, k = i & 127;
        xs[j][k] = g_qstar[(g0 + j) * 128 + k];
    }
    const int ihbase[3] = { 0, 49152, 81920 };
    const int hhbase[3] = { 32768, 65536, 98304 };
    for (int l = 0; l < 3; l++) {
        int nk4 = l ? 16 : 32;
        for (int i = tid; i < 512; i += 256) {
            int j = i >> 6, d = i & 63;
            hp[j][d] = g_lh[l * NGR * 64 + (g0 + j) * 64 + d];
            cp[j][d] = g_lc[l * NGR * 64 + (g0 + j) * 64 + d];
        }
        __syncthreads();
        float acc[8];
        float bs = g_bsum[l * 256 + tid];
#pragma unroll
        for (int j = 0; j < 8; j++) acc[j] = bs;
        const float4* Wi = (const float4*)(g_wtl + ihbase[l]) + tid;
        for (int k4 = 0; k4 < nk4; k4++) {
            float4 w = Wi[k4 * 256];
#pragma unroll
            for (int j = 0; j < 8; j++) {
                float4 xv = *(const float4*)&xs[j][k4 * 4];
                acc[j] = fmaf(w.x, xv.x, fmaf(w.y, xv.y, fmaf(w.z, xv.z, fmaf(w.w, xv.w, acc[j]))));
            }
        }
        const float4* Wh = (const float4*)(g_wtl + hhbase[l]) + tid;
        for (int k4 = 0; k4 < 16; k4++) {
            float4 w = Wh[k4 * 256];
#pragma unroll
            for (int j = 0; j < 8; j++) {
                float4 hv = *(const float4*)&hp[j][k4 * 4];
                acc[j] = fmaf(w.x, hv.x, fmaf(w.y, hv.y, fmaf(w.z, hv.z, fmaf(w.w, hv.w, acc[j]))));
            }
        }
#pragma unroll
        for (int j = 0; j < 8; j++) gs[j][tid] = acc[j];
        __syncthreads();
        for (int i = tid; i < 512; i += 256) {
            int j = i >> 6, d = i & 63;
            float c = sigf(gs[j][64 + d]) * cp[j][d] + sigf(gs[j][d]) * tanhfast(gs[j][128 + d]);
            float hn = sigf(gs[j][192 + d]) * tanhfast(c);
            g_lc[l * NGR * 64 + (g0 + j) * 64 + d] = c;
            g_lh[l * NGR * 64 + (g0 + j) * 64 + d] = hn;
            xs[j][d] = hn;
            if (l == 2) g_q[(g0 + j) * 64 + d] = hn;
        }
        __syncthreads();
    }
}

// ---------------- attention: one CTA per graph ----------------
#define AP 68
#define ATT_SMEM ((13600 + 64 + 64 + 200 + 256) * 4)

__global__ __launch_bounds__(256, 2) void attn_kernel(
    const float* __restrict__ Wp, const float* __restrict__ bp,
    float* __restrict__ out, int last) {
    extern __shared__ float smf[];
    float* hs    = smf;
    float* qv    = smf + 13600;
    float* red   = smf + 13664;
    float* alpha = smf + 13728;
    float* part  = smf + 13928;
    const int tid = threadIdx.x;
    const int g = blockIdx.x;
    const int lane = tid & 31;
    const int wrp = tid >> 5;

    for (int i = tid; i < 3200; i += 256) {
        int n = i >> 4, c4 = i & 15;
        *(float4*)&hs[n * AP + c4 * 4] = *(const float4*)(g_hA + (g * NPG + n) * 64 + c4 * 4);
    }
    if (tid < 64) qv[tid] = g_q[g * 64 + tid];
    __syncthreads();

    float e = -3.4e38f;
    if (tid < NPG) {
        float a = 0.0f;
#pragma unroll 4
        for (int c4 = 0; c4 < 16; c4++) {
            float4 hv = *(const float4*)&hs[tid * AP + c4 * 4];
            float4 q4 = *(const float4*)&qv[c4 * 4];
            a = fmaf(hv.x, q4.x, fmaf(hv.y, q4.y, fmaf(hv.z, q4.z, fmaf(hv.w, q4.w, a))));
        }
        e = a;
    }
    float m = e;
#pragma unroll
    for (int o = 16; o >= 1; o >>= 1) m = fmaxf(m, __shfl_xor_sync(0xffffffffu, m, o));
    if (lane == 0) red[wrp] = m;
    __syncthreads();
    if (tid == 0) {
        float mm = red[0];
        for (int w = 1; w < 8; w++) mm = fmaxf(mm, red[w]);
        red[32] = mm;
    }
    __syncthreads();
    float ex = (tid < NPG) ? __expf(e - red[32]) : 0.0f;
    float ss = ex;
#pragma unroll
    for (int o = 16; o >= 1; o >>= 1) ss += __shfl_xor_sync(0xffffffffu, ss, o);
    if (lane == 0) red[wrp] = ss;
    __syncthreads();
    if (tid == 0) {
        float s = 0.0f;
        for (int w = 0; w < 8; w++) s += red[w];
        red[33] = s;
    }
    __syncthreads();
    if (tid < NPG) alpha[tid] = ex / red[33];
    __syncthreads();
    {
        int d = tid & 63, grp = tid >> 6;
        float a = 0.0f;
        int nlo = grp * 50;
        for (int n = nlo; n < nlo + 50; n++)
            a = fmaf(hs[n * AP + d], alpha[n], a);
        part[tid] = a;
    }
    __syncthreads();
    if (tid < 64) {
        float ro = part[tid] + part[64 + tid] + part[128 + tid] + part[192 + tid];
        g_qstar[g * 128 + tid] = qv[tid];
        g_qstar[g * 128 + 64 + tid] = ro;
    }
    if (last) {
        __syncthreads();
        if (tid < 3) {
            float a = bp[tid];
            for (int j = 0; j < 128; j++)
                a = fmaf(g_qstar[g * 128 + j], Wp[tid * 128 + j], a);
            out[g * 3 + tid] = a;
        }
    }
}

extern "C" void kernel_launch(void* const* d_in, const int* in_sizes, int n_in,
                              void* d_out, int out_size) {
    const float* feats  = (const float*)d_in[0];
    const float* W_edge = (const float*)d_in[1];
    const float* b_edge = (const float*)d_in[2];
    const float* gWih   = (const float*)d_in[3];
    const float* gWhh   = (const float*)d_in[4];
    const float* gbih   = (const float*)d_in[5];
    const float* gbhh   = (const float*)d_in[6];
    const float* wih0 = (const float*)d_in[7];
    const float* whh0 = (const float*)d_in[8];
    const float* bih0 = (const float*)d_in[9];
    const float* bhh0 = (const float*)d_in[10];
    const float* wih1 = (const float*)d_in[11];
    const float* whh1 = (const float*)d_in[12];
    const float* bih1 = (const float*)d_in[13];
    const float* bhh1 = (const float*)d_in[14];
    const float* wih2 = (const float*)d_in[15];
    const float* whh2 = (const float*)d_in[16];
    const float* bih2 = (const float*)d_in[17];
    const float* bhh2 = (const float*)d_in[18];
    const float* Wp   = (const float*)d_in[19];
    const float* bp   = (const float*)d_in[20];
    const int* src    = (const int*)d_in[21];
    const int* dst    = (const int*)d_in[22];
    const int* ety    = (const int*)d_in[23];
    float* out = (float*)d_out;

    static int inited = 0;
    if (!inited) {
        cudaFuncSetAttribute(step_kernel,
                             cudaFuncAttributeMaxDynamicSharedMemorySize, ST_SMEM);
        cudaFuncSetAttribute(attn_kernel,
                             cudaFuncAttributeMaxDynamicSharedMemorySize, ATT_SMEM);
        inited = 1;
    }

    prep_kernel<<<192, 256>>>(W_edge, gWih, gWhh);
    prep_lstm<<<452, 256>>>(wih0, whh0, bih0, bhh0,
                            wih1, whh1, bih1, bhh1,
                            wih2, whh2, bih2, bhh2);
    sort_kernel<<<NGR, 640>>>(src, dst, ety);
    for (int s = 0; s < 5; s++)
        step_kernel<<<NGR * 2, NTH, ST_SMEM>>>(feats, b_edge, gbih, gbhh, s);
    for (int it = 0; it < 6; it++) {
        lstm_kernel<<<40, 256>>>();
        attn_kernel<<<NGR, 256, ATT_SMEM>>>(Wp, bp, out, it == 5 ? 1 : 0);
    }
}

// round 13
// speedup vs baseline: 3.8740x; 1.0003x over previous
#include <cuda_runtime.h>
#include <cuda_bf16.h>
#include <math.h>

// GGNN + Set2Set. R8: step kernel gathers over fp32 h (no bf16 decode),
// own-half bf16-pair h built via SMEM phase overlay, packed B fragments
// (1 LDS.128/mma-group), init_state folded into prep_lstm.

#define NPG 200
#define EPG 3200
#define NET 6
#define NGR 320
#define NTH 448

// ---- step kernel SMEM layout (bytes) ----
#define H_F32 0              // 200 rows x 288B (fp32 h, bank-rotated pitch)
#define SP_HI 57600          // 112 rows x 128B (s/a hi)
#define SP_LO 71936
#define WB    86272          // 16384B staged B fragments
#define ESRCB 102656         // 3200B
#define OFFLB 105856         // 606 u16 (pad)
#define ST_SMEM 107072
// HP pair (own half, built in phase B) overlays H_F32:
//   half==0 -> base 28928 (reads rows 0..99 at 0..28800)
//   half==1 -> base 0     (reads rows 100..199 at 28800..57600)

// ---------------- global scratch ----------------
__device__ float g_hA[64000 * 64];
__device__ float g_hB[64000 * 64];
__device__ unsigned char  g_esrc[NGR * EPG];
__device__ unsigned short g_off[NGR * 1216];
// B fragments: [tile][ (ntg*4+ks)*32 + lane ] = uint4 {hi_r0, hi_r1, lo_r0, lo_r1}
__device__ unsigned int g_wfrag[12 * 4096];
// set2set state
__device__ float g_qstar[NGR * 128];
__device__ float g_lh[3 * NGR * 64];
__device__ float g_lc[3 * NGR * 64];
__device__ float g_q[NGR * 64];
__device__ float g_wtl[114688];
__device__ float g_bsum[768];

__device__ __forceinline__ float sigf(float x) { return 1.0f / (1.0f + __expf(-x)); }
__device__ __forceinline__ float tanhfast(float x) {
    x = fminf(fmaxf(x, -15.0f), 15.0f);
    float e = __expf(2.0f * x);
    return (e - 1.0f) / (e + 1.0f);
}
__device__ __forceinline__ float blo(unsigned w) { return __uint_as_float(w << 16); }
__device__ __forceinline__ float bhi(unsigned w) { return __uint_as_float(w & 0xffff0000u); }
__device__ __forceinline__ void cvtpair(float a, float b, unsigned& hi, unsigned& lo) {
    asm("cvt.rn.bf16x2.f32 %0, %1, %2;" : "=r"(hi) : "f"(b), "f"(a));
    float fa = blo(hi), fb = bhi(hi);
    asm("cvt.rn.bf16x2.f32 %0, %1, %2;" : "=r"(lo) : "f"(b - fb), "f"(a - fa));
}
__device__ __forceinline__ unsigned smem_u32(const void* p) {
    unsigned a;
    asm("{ .reg .u64 t; cvta.to.shared.u64 t, %1; cvt.u32.u64 %0, t; }" : "=r"(a) : "l"(p));
    return a;
}
__device__ __forceinline__ void ldmA(unsigned addr, unsigned r[4]) {
    asm volatile("ldmatrix.sync.aligned.m8n8.x4.shared.b16 {%0,%1,%2,%3}, [%4];"
                 : "=r"(r[0]), "=r"(r[1]), "=r"(r[2]), "=r"(r[3]) : "r"(addr));
}
__device__ __forceinline__ void mma16816(float* c, const unsigned a[4], unsigned b0, unsigned b1) {
    asm volatile("mma.sync.aligned.m16n8k16.row.col.f32.bf16.bf16.f32 "
                 "{%0,%1,%2,%3}, {%4,%5,%6,%7}, {%8,%9}, {%0,%1,%2,%3};"
                 : "+f"(c[0]), "+f"(c[1]), "+f"(c[2]), "+f"(c[3])
                 : "r"(a[0]), "r"(a[1]), "r"(a[2]), "r"(a[3]), "r"(b0), "r"(b1));
}

// ---------------- prep: bake packed B fragments ----------------
__global__ void prep_kernel(const float* __restrict__ W_edge,
                            const float* __restrict__ gWih,
                            const float* __restrict__ gWhh) {
    int i = blockIdx.x * blockDim.x + threadIdx.x;
    if (i >= 49152) return;
    int word = i & 3, lane = (i >> 2) & 31, ks = (i >> 7) & 3;
    int ntg = (i >> 9) & 7, tile = i >> 12;
    int reg = word & 1, split = word >> 1;
    int n = ntg * 8 + (lane >> 2);
    int k = ks * 16 + (lane & 3) * 2 + reg * 8;
    float w0, w1;
    if (tile < 6) {
        w0 = W_edge[(tile * 64 + k) * 64 + n];
        w1 = W_edge[(tile * 64 + k + 1) * 64 + n];
    } else {
        int p = tile - 6;
        const int g0s[6] = { 0, 0, 128, 128, 64, 64 };
        const float* M = (p == 0 || p == 3 || p == 4) ? gWih : gWhh;
        w0 = M[(g0s[p] + n) * 64 + k];
        w1 = M[(g0s[p] + n) * 64 + k + 1];
    }
    unsigned hw, lw;
    cvtpair(w0, w1, hw, lw);
    g_wfrag[tile * 4096 + (((ntg * 4 + ks) * 32 + lane) << 2) + word] = split ? lw : hw;
}

// ---------------- prep: lstm weights + bias sums + state init ----------------
__global__ void prep_lstm(const float* __restrict__ wih0, const float* __restrict__ whh0,
                          const float* __restrict__ bih0, const float* __restrict__ bhh0,
                          const float* __restrict__ wih1, const float* __restrict__ whh1,
                          const float* __restrict__ bih1, const float* __restrict__ bhh1,
                          const float* __restrict__ wih2, const float* __restrict__ whh2,
                          const float* __restrict__ bih2, const float* __restrict__ bhh2) {
    int i = blockIdx.x * blockDim.x + threadIdx.x;
    if (i < 114688) {
        const int   bases[6]  = { 0, 32768, 49152, 65536, 81920, 98304 };
        const int   indims[6] = { 128, 64, 64, 64, 64, 64 };
        const float* Ws[6] = { wih0, whh0, wih1, whh1, wih2, whh2 };
        int seg = 5;
#pragma unroll
        for (int s = 0; s < 5; s++) if (i < bases[s + 1]) { seg = s; break; }
        int idx = i - bases[seg];
        int k4 = idx >> 10, r = idx & 1023, t = r >> 2, kk = r & 3;
        g_wtl[i] = Ws[seg][t * indims[seg] + k4 * 4 + kk];
    } else if (i < 115456) {
        int i2 = i - 114688;
        int l = i2 >> 8, t = i2 & 255;
        const float* bi = (l == 0) ? bih0 : (l == 1) ? bih1 : bih2;
        const float* bh = (l == 0) ? bhh0 : (l == 1) ? bhh1 : bhh2;
        g_bsum[i2] = bi[t] + bh[t];
    }
    if (i < NGR * 128) g_qstar[i] = 0.0f;
    if (i < 3 * NGR * 64) { g_lh[i] = 0.0f; g_lc[i] = 0.0f; }
}

// ---------------- sort ----------------
__global__ __launch_bounds__(640) void sort_kernel(
    const int* __restrict__ g_src, const int* __restrict__ g_dst,
    const int* __restrict__ g_ety) {
    __shared__ int cnt[1280];
    __shared__ int csum[256];
    const int tid = threadIdx.x;
    const int g = blockIdx.x;
    const int nbase = g * NPG, ebase = g * EPG;
    for (int i = tid; i < 1280; i += 640) cnt[i] = 0;
    __syncthreads();
    for (int e = tid; e < EPG; e += 640) {
        int key = g_ety[ebase + e] * NPG + (g_dst[ebase + e] - nbase);
        atomicAdd(&cnt[key], 1);
    }
    __syncthreads();
    if (tid < 256) {
        int s = 0;
#pragma unroll
        for (int j = 0; j < 5; j++) s += cnt[tid * 5 + j];
        csum[tid] = s;
    }
    __syncthreads();
    if (tid < 32) {
        int s = 0;
#pragma unroll
        for (int j = 0; j < 8; j++) s += csum[tid * 8 + j];
        int v = s;
        for (int o = 1; o < 32; o <<= 1) {
            int u = __shfl_up_sync(0xffffffffu, v, o);
            if (tid >= o) v += u;
        }
        int run = v - s;
#pragma unroll
        for (int j = 0; j < 8; j++) {
            int c = csum[tid * 8 + j];
            csum[tid * 8 + j] = run;
            run += c;
        }
    }
    __syncthreads();
    if (tid < 256) {
        int run = csum[tid];
#pragma unroll
        for (int j = 0; j < 5; j++) {
            int idx = tid * 5 + j;
            int c = cnt[idx];
            if (idx < 1216) g_off[g * 1216 + idx] = (unsigned short)run;
            run += c;
        }
    }
    __syncthreads();
    if (tid < 256) {
        int run = csum[tid];
#pragma unroll
        for (int j = 0; j < 5; j++) {
            int idx = tid * 5 + j;
            int c = cnt[idx];
            cnt[idx] = run;
            run += c;
        }
    }
    __syncthreads();
    for (int e = tid; e < EPG; e += 640) {
        int key = g_ety[ebase + e] * NPG + (g_dst[ebase + e] - nbase);
        int pos = atomicAdd(&cnt[key], 1);
        g_esrc[g * EPG + pos] = (unsigned char)(g_src[ebase + e] - nbase);
    }
}

// ---------------- step kernel ----------------
__global__ __launch_bounds__(NTH, 2) void step_kernel(
    const float* __restrict__ feats,
    const float* __restrict__ b_edge,
    const float* __restrict__ gbih,
    const float* __restrict__ gbhh,
    int step) {
    extern __shared__ char sm[];
    unsigned smb = smem_u32(sm);
    unsigned char* esrc = (unsigned char*)(sm + ESRCB);
    unsigned short* offl = (unsigned short*)(sm + OFFLB);

    const int tid = threadIdx.x;
    const int g = blockIdx.x >> 1;
    const int half = blockIdx.x & 1;
    const int lane = tid & 31;
    const int wid = tid >> 5;
    const int mt = wid >> 1;
    const int nh = wid & 1;
    const int lrow = mt * 16 + (lane & 15);
    const int lmt = lane >> 4;
    const int g8 = lane >> 2, q = lane & 3;
    const int r1l = mt * 16 + g8, r2l = r1l + 8;
    const int hpb = half ? 0 : 28928;      // HP pair base (overlay on H_F32)

    const float* hsrc = (step == 0) ? feats : ((step & 1) ? g_hA : g_hB);
    float* hdst = (step & 1) ? g_hB : g_hA;

    // ---- load: full-graph h fp32 (pitch 288B), esrc, own-half offsets ----
    for (int i = tid; i < 3200; i += NTH) {
        int n = i >> 4, c4 = i & 15;
        *(float4*)(sm + H_F32 + n * 288 + c4 * 16) =
            *(const float4*)(hsrc + (g * NPG + n) * 64 + c4 * 4);
    }
    {
        const uint4* es = (const uint4*)(g_esrc + g * EPG);
        for (int i = tid; i < 200; i += NTH) ((uint4*)esrc)[i] = es[i];
        for (int j = tid; j < 606; j += NTH) {
            int t = j / 101, i2 = j % 101;
            offl[j] = g_off[g * 1216 + t * 200 + half * 100 + i2];
        }
    }

    // ---- etype passes: aC = sum_t (S_t @ W_t) ----
    float aC[16];
#pragma unroll
    for (int i = 0; i < 16; i++) aC[i] = 0.0f;

    for (int t = 0; t < NET; t++) {
        const uint4* ws = (const uint4*)g_wfrag + t * 1024;
        uint4 w0 = ws[tid], w1 = ws[tid + 448], w2;
        if (tid < 128) w2 = ws[tid + 896];
        __syncthreads();
        ((uint4*)(sm + WB))[tid] = w0;
        ((uint4*)(sm + WB))[tid + 448] = w1;
        if (tid < 128) ((uint4*)(sm + WB))[tid + 896] = w2;
        // fp32 gather -> s bf16 pair (own half)
        for (int i = tid; i < 800; i += NTH) {
            int n = i >> 3, u = i & 7;
            int b = t * 101 + n;
            int j0 = offl[b], j1 = offl[b + 1];
            float4 s0 = make_float4(0.f, 0.f, 0.f, 0.f);
            float4 s1 = make_float4(0.f, 0.f, 0.f, 0.f);
            for (int j = j0; j < j1; j++) {
                const float4* h4 = (const float4*)(sm + H_F32 + (int)esrc[j] * 288 + u * 32);
                float4 v0 = h4[0], v1 = h4[1];
                s0.x += v0.x; s0.y += v0.y; s0.z += v0.z; s0.w += v0.w;
                s1.x += v1.x; s1.y += v1.y; s1.z += v1.z; s1.w += v1.w;
            }
            unsigned hw0, lw0, hw1, lw1, hw2, lw2, hw3, lw3;
            cvtpair(s0.x, s0.y, hw0, lw0);
            cvtpair(s0.z, s0.w, hw1, lw1);
            cvtpair(s1.x, s1.y, hw2, lw2);
            cvtpair(s1.z, s1.w, hw3, lw3);
            int bo = n * 128 + (((u + n) & 7) << 4);
            *(uint4*)(sm + SP_HI + bo) = make_uint4(hw0, hw1, hw2, hw3);
            *(uint4*)(sm + SP_LO + bo) = make_uint4(lw0, lw1, lw2, lw3);
        }
        __syncthreads();
#pragma unroll
        for (int ks = 0; ks < 4; ks++) {
            int unit = 2 * ks + lmt;
            unsigned ah[4], al[4];
            ldmA(smb + SP_HI + lrow * 128 + (((unit + lrow) & 7) << 4), ah);
            ldmA(smb + SP_LO + lrow * 128 + (((unit + lrow) & 7) << 4), al);
#pragma unroll
            for (int nt = 0; nt < 4; nt++) {
                int ntg = nh * 4 + nt;
                uint4 bb = *(const uint4*)(sm + WB + (((ntg * 4 + ks) * 32 + lane) << 4));
                mma16816(aC + nt * 4, al, bb.x, bb.y);
                mma16816(aC + nt * 4, ah, bb.z, bb.w);
                mma16816(aC + nt * 4, ah, bb.x, bb.y);
            }
        }
    }
    // bias: aC += cnt_t(row) * b_edge[t][col]
#pragma unroll
    for (int t = 0; t < NET; t++) {
        float c1 = (r1l < 100) ? (float)(offl[t * 101 + r1l + 1] - offl[t * 101 + r1l]) : 0.0f;
        float c2 = (r2l < 100) ? (float)(offl[t * 101 + r2l + 1] - offl[t * 101 + r2l]) : 0.0f;
#pragma unroll
        for (int nt = 0; nt < 4; nt++) {
            int col = nh * 32 + nt * 8 + q * 2;
            float2 b = *(const float2*)(b_edge + t * 64 + col);
            aC[nt * 4 + 0] = fmaf(c1, b.x, aC[nt * 4 + 0]);
            aC[nt * 4 + 1] = fmaf(c1, b.y, aC[nt * 4 + 1]);
            aC[nt * 4 + 2] = fmaf(c2, b.x, aC[nt * 4 + 2]);
            aC[nt * 4 + 3] = fmaf(c2, b.y, aC[nt * 4 + 3]);
        }
    }
    __syncthreads();   // all mma reads of SP + all gathers of H_F32 done
    // write a -> SP bf16 pair
#pragma unroll
    for (int nt = 0; nt < 4; nt++) {
        int col = nh * 32 + nt * 8 + q * 2;
        int u = col >> 3;
        unsigned hw, lw;
        cvtpair(aC[nt * 4 + 0], aC[nt * 4 + 1], hw, lw);
        int bo1 = r1l * 128 + (((u + r1l) & 7) << 4) + q * 4;
        *(unsigned*)(sm + SP_HI + bo1) = hw;
        *(unsigned*)(sm + SP_LO + bo1) = lw;
        cvtpair(aC[nt * 4 + 2], aC[nt * 4 + 3], hw, lw);
        int bo2 = r2l * 128 + (((u + r2l) & 7) << 4) + q * 4;
        *(unsigned*)(sm + SP_HI + bo2) = hw;
        *(unsigned*)(sm + SP_LO + bo2) = lw;
    }
    // build HP pair (own half) from H_F32 into disjoint overlay region
    for (int i = tid; i < 800; i += NTH) {
        int r = i >> 3, u = i & 7;
        const float4* h4 = (const float4*)(sm + H_F32 + (half * 100 + r) * 288 + u * 32);
        float4 v0 = h4[0], v1 = h4[1];
        unsigned hw0, lw0, hw1, lw1, hw2, lw2, hw3, lw3;
        cvtpair(v0.x, v0.y, hw0, lw0);
        cvtpair(v0.z, v0.w, hw1, lw1);
        cvtpair(v1.x, v1.y, hw2, lw2);
        cvtpair(v1.z, v1.w, hw3, lw3);
        int bo = r * 128 + (((u + r) & 7) << 4);
        *(uint4*)(sm + hpb + bo) = make_uint4(hw0, hw1, hw2, hw3);
        *(uint4*)(sm + hpb + 14336 + bo) = make_uint4(lw0, lw1, lw2, lw3);
    }

    // ---- GRU ----
#define STAGEW(T) do { \
        const uint4* ws_ = (const uint4*)g_wfrag + (T) * 1024; \
        uint4 s0 = ws_[tid], s1 = ws_[tid + 448], s2; \
        if (tid < 128) s2 = ws_[tid + 896]; \
        __syncthreads(); \
        ((uint4*)(sm + WB))[tid] = s0; \
        ((uint4*)(sm + WB))[tid + 448] = s1; \
        if (tid < 128) ((uint4*)(sm + WB))[tid + 896] = s2; \
        __syncthreads(); \
    } while (0)

#define MMPASS(BASE_HI, BASE_LO, ROW, C) do { \
        _Pragma("unroll") \
        for (int ks = 0; ks < 4; ks++) { \
            int unit = 2 * ks + lmt; \
            unsigned ah[4], al[4]; \
            ldmA(smb + (BASE_HI) + (ROW) * 128 + (((unit + (ROW)) & 7) << 4), ah); \
            ldmA(smb + (BASE_LO) + (ROW) * 128 + (((unit + (ROW)) & 7) << 4), al); \
            _Pragma("unroll") \
            for (int nt = 0; nt < 4; nt++) { \
                int ntg = nh * 4 + nt; \
                uint4 bb = *(const uint4*)(sm + WB + (((ntg * 4 + ks) * 32 + lane) << 4)); \
                mma16816((C) + nt * 4, al, bb.x, bb.y); \
                mma16816((C) + nt * 4, ah, bb.z, bb.w); \
                mma16816((C) + nt * 4, ah, bb.x, bb.y); \
            } \
        } \
    } while (0)

    float C[16], rg[16];
    // r = sigmoid(a@Wih_r + h@Whh_r + b)
#pragma unroll
    for (int i = 0; i < 16; i++) C[i] = 0.0f;
    STAGEW(6);  MMPASS(SP_HI, SP_LO, lrow, C);
    STAGEW(7);  MMPASS(hpb, hpb + 14336, lrow, C);
#pragma unroll
    for (int nt = 0; nt < 4; nt++) {
        int col = nh * 32 + nt * 8 + q * 2;
        float2 bi = *(const float2*)(gbih + col);
        float2 bh = *(const float2*)(gbhh + col);
        rg[nt * 4 + 0] = sigf(C[nt * 4 + 0] + bi.x + bh.x);
        rg[nt * 4 + 1] = sigf(C[nt * 4 + 1] + bi.y + bh.y);
        rg[nt * 4 + 2] = sigf(C[nt * 4 + 2] + bi.x + bh.x);
        rg[nt * 4 + 3] = sigf(C[nt * 4 + 3] + bi.y + bh.y);
    }
    // t = r * (h@Whh_n + bhh_n)
#pragma unroll
    for (int i = 0; i < 16; i++) C[i] = 0.0f;
    STAGEW(8);  MMPASS(hpb, hpb + 14336, lrow, C);
#pragma unroll
    for (int nt = 0; nt < 4; nt++) {
        int col = nh * 32 + nt * 8 + q * 2;
        float2 bh = *(const float2*)(gbhh + 128 + col);
        rg[nt * 4 + 0] *= (C[nt * 4 + 0] + bh.x);
        rg[nt * 4 + 1] *= (C[nt * 4 + 1] + bh.y);
        rg[nt * 4 + 2] *= (C[nt * 4 + 2] + bh.x);
        rg[nt * 4 + 3] *= (C[nt * 4 + 3] + bh.y);
    }
    // n = tanh(a@Wih_n + bih_n + t)
#pragma unroll
    for (int i = 0; i < 16; i++) C[i] = 0.0f;
    STAGEW(9);  MMPASS(SP_HI, SP_LO, lrow, C);
#pragma unroll
    for (int nt = 0; nt < 4; nt++) {
        int col = nh * 32 + nt * 8 + q * 2;
        float2 bi = *(const float2*)(gbih + 128 + col);
        rg[nt * 4 + 0] = tanhfast(C[nt * 4 + 0] + bi.x + rg[nt * 4 + 0]);
        rg[nt * 4 + 1] = tanhfast(C[nt * 4 + 1] + bi.y + rg[nt * 4 + 1]);
        rg[nt * 4 + 2] = tanhfast(C[nt * 4 + 2] + bi.x + rg[nt * 4 + 2]);
        rg[nt * 4 + 3] = tanhfast(C[nt * 4 + 3] + bi.y + rg[nt * 4 + 3]);
    }
    // z = sigmoid(a@Wih_z + h@Whh_z + b); h' = n + z*(h - n)
#pragma unroll
    for (int i = 0; i < 16; i++) C[i] = 0.0f;
    STAGEW(10); MMPASS(SP_HI, SP_LO, lrow, C);
    STAGEW(11); MMPASS(hpb, hpb + 14336, lrow, C);
#pragma unroll
    for (int nt = 0; nt < 4; nt++) {
        int col = nh * 32 + nt * 8 + q * 2;
        int u = col >> 3;
        float2 bi = *(const float2*)(gbih + 64 + col);
        float2 bh2 = *(const float2*)(gbhh + 64 + col);
        if (r1l < 100) {
            int bo = r1l * 128 + (((u + r1l) & 7) << 4) + q * 4;
            unsigned hw = *(const unsigned*)(sm + hpb + bo);
            unsigned lw = *(const unsigned*)(sm + hpb + 14336 + bo);
            float h0 = blo(hw) + blo(lw), h1 = bhi(hw) + bhi(lw);
            float z0 = sigf(C[nt * 4 + 0] + bi.x + bh2.x);
            float z1 = sigf(C[nt * 4 + 1] + bi.y + bh2.y);
            float n0 = rg[nt * 4 + 0], n1 = rg[nt * 4 + 1];
            float2 o;
            o.x = fmaf(z0, h0 - n0, n0);
            o.y = fmaf(z1, h1 - n1, n1);
            *(float2*)(hdst + (g * NPG + half * 100 + r1l) * 64 + col) = o;
        }
        if (r2l < 100) {
            int bo = r2l * 128 + (((u + r2l) & 7) << 4) + q * 4;
            unsigned hw = *(const unsigned*)(sm + hpb + bo);
            unsigned lw = *(const unsigned*)(sm + hpb + 14336 + bo);
            float h0 = blo(hw) + blo(lw), h1 = bhi(hw) + bhi(lw);
            float z0 = sigf(C[nt * 4 + 2] + bi.x + bh2.x);
            float z1 = sigf(C[nt * 4 + 3] + bi.y + bh2.y);
            float n0 = rg[nt * 4 + 2], n1 = rg[nt * 4 + 3];
            float2 o;
            o.x = fmaf(z0, h0 - n0, n0);
            o.y = fmaf(z1, h1 - n1, n1);
            *(float2*)(hdst + (g * NPG + half * 100 + r2l) * 64 + col) = o;
        }
    }
#undef STAGEW
#undef MMPASS
}

// ---------------- batched LSTM: 40 CTAs x 8 graphs ----------------
__global__ __launch_bounds__(256) void lstm_kernel() {
    __shared__ float xs[8][128];
    __shared__ float hp[8][64];
    __shared__ float cp[8][64];
    __shared__ float gs[8][256];
    const int tid = threadIdx.x;
    const int g0 = blockIdx.x * 8;
    for (int i = tid; i < 1024; i += 256) {
        int j = i >> 7, k = i & 127;
        xs[j][k] = g_qstar[(g0 + j) * 128 + k];
    }
    const int ihbase[3] = { 0, 49152, 81920 };
    const int hhbase[3] = { 32768, 65536, 98304 };
    for (int l = 0; l < 3; l++) {
        int nk4 = l ? 16 : 32;
        for (int i = tid; i < 512; i += 256) {
            int j = i >> 6, d = i & 63;
            hp[j][d] = g_lh[l * NGR * 64 + (g0 + j) * 64 + d];
            cp[j][d] = g_lc[l * NGR * 64 + (g0 + j) * 64 + d];
        }
        __syncthreads();
        float acc[8];
        float bs = g_bsum[l * 256 + tid];
#pragma unroll
        for (int j = 0; j < 8; j++) acc[j] = bs;
        const float4* Wi = (const float4*)(g_wtl + ihbase[l]) + tid;
        for (int k4 = 0; k4 < nk4; k4++) {
            float4 w = Wi[k4 * 256];
#pragma unroll
            for (int j = 0; j < 8; j++) {
                float4 xv = *(const float4*)&xs[j][k4 * 4];
                acc[j] = fmaf(w.x, xv.x, fmaf(w.y, xv.y, fmaf(w.z, xv.z, fmaf(w.w, xv.w, acc[j]))));
            }
        }
        const float4* Wh = (const float4*)(g_wtl + hhbase[l]) + tid;
        for (int k4 = 0; k4 < 16; k4++) {
            float4 w = Wh[k4 * 256];
#pragma unroll
            for (int j = 0; j < 8; j++) {
                float4 hv = *(const float4*)&hp[j][k4 * 4];
                acc[j] = fmaf(w.x, hv.x, fmaf(w.y, hv.y, fmaf(w.z, hv.z, fmaf(w.w, hv.w, acc[j]))));
            }
        }
#pragma unroll
        for (int j = 0; j < 8; j++) gs[j][tid] = acc[j];
        __syncthreads();
        for (int i = tid; i < 512; i += 256) {
            int j = i >> 6, d = i & 63;
            float c = sigf(gs[j][64 + d]) * cp[j][d] + sigf(gs[j][d]) * tanhfast(gs[j][128 + d]);
            float hn = sigf(gs[j][192 + d]) * tanhfast(c);
            g_lc[l * NGR * 64 + (g0 + j) * 64 + d] = c;
            g_lh[l * NGR * 64 + (g0 + j) * 64 + d] = hn;
            xs[j][d] = hn;
            if (l == 2) g_q[(g0 + j) * 64 + d] = hn;
        }
        __syncthreads();
    }
}

// ---------------- attention: one CTA per graph ----------------
#define AP 68
#define ATT_SMEM ((13600 + 64 + 64 + 200 + 256) * 4)

__global__ __launch_bounds__(256, 2) void attn_kernel(
    const float* __restrict__ Wp, const float* __restrict__ bp,
    float* __restrict__ out, int last) {
    extern __shared__ float smf[];
    float* hs    = smf;
    float* qv    = smf + 13600;
    float* red   = smf + 13664;
    float* alpha = smf + 13728;
    float* part  = smf + 13928;
    const int tid = threadIdx.x;
    const int g = blockIdx.x;
    const int lane = tid & 31;
    const int wrp = tid >> 5;

    for (int i = tid; i < 3200; i += 256) {
        int n = i >> 4, c4 = i & 15;
        *(float4*)&hs[n * AP + c4 * 4] = *(const float4*)(g_hA + (g * NPG + n) * 64 + c4 * 4);
    }
    if (tid < 64) qv[tid] = g_q[g * 64 + tid];
    __syncthreads();

    float e = -3.4e38f;
    if (tid < NPG) {
        float a = 0.0f;
#pragma unroll 4
        for (int c4 = 0; c4 < 16; c4++) {
            float4 hv = *(const float4*)&hs[tid * AP + c4 * 4];
            float4 q4 = *(const float4*)&qv[c4 * 4];
            a = fmaf(hv.x, q4.x, fmaf(hv.y, q4.y, fmaf(hv.z, q4.z, fmaf(hv.w, q4.w, a))));
        }
        e = a;
    }
    float m = e;
#pragma unroll
    for (int o = 16; o >= 1; o >>= 1) m = fmaxf(m, __shfl_xor_sync(0xffffffffu, m, o));
    if (lane == 0) red[wrp] = m;
    __syncthreads();
    if (tid == 0) {
        float mm = red[0];
        for (int w = 1; w < 8; w++) mm = fmaxf(mm, red[w]);
        red[32] = mm;
    }
    __syncthreads();
    float ex = (tid < NPG) ? __expf(e - red[32]) : 0.0f;
    float ss = ex;
#pragma unroll
    for (int o = 16; o >= 1; o >>= 1) ss += __shfl_xor_sync(0xffffffffu, ss, o);
    if (lane == 0) red[wrp] = ss;
    __syncthreads();
    if (tid == 0) {
        float s = 0.0f;
        for (int w = 0; w < 8; w++) s += red[w];
        red[33] = s;
    }
    __syncthreads();
    if (tid < NPG) alpha[tid] = ex / red[33];
    __syncthreads();
    {
        int d = tid & 63, grp = tid >> 6;
        float a = 0.0f;
        int nlo = grp * 50;
        for (int n = nlo; n < nlo + 50; n++)
            a = fmaf(hs[n * AP + d], alpha[n], a);
        part[tid] = a;
    }
    __syncthreads();
    if (tid < 64) {
        float ro = part[tid] + part[64 + tid] + part[128 + tid] + part[192 + tid];
        g_qstar[g * 128 + tid] = qv[tid];
        g_qstar[g * 128 + 64 + tid] = ro;
    }
    if (last) {
        __syncthreads();
        if (tid < 3) {
            float a = bp[tid];
            for (int j = 0; j < 128; j++)
                a = fmaf(g_qstar[g * 128 + j], Wp[tid * 128 + j], a);
            out[g * 3 + tid] = a;
        }
    }
}

extern "C" void kernel_launch(void* const* d_in, const int* in_sizes, int n_in,
                              void* d_out, int out_size) {
    const float* feats  = (const float*)d_in[0];
    const float* W_edge = (const float*)d_in[1];
    const float* b_edge = (const float*)d_in[2];
    const float* gWih   = (const float*)d_in[3];
    const float* gWhh   = (const float*)d_in[4];
    const float* gbih   = (const float*)d_in[5];
    const float* gbhh   = (const float*)d_in[6];
    const float* wih0 = (const float*)d_in[7];
    const float* whh0 = (const float*)d_in[8];
    const float* bih0 = (const float*)d_in[9];
    const float* bhh0 = (const float*)d_in[10];
    const float* wih1 = (const float*)d_in[11];
    const float* whh1 = (const float*)d_in[12];
    const float* bih1 = (const float*)d_in[13];
    const float* bhh1 = (const float*)d_in[14];
    const float* wih2 = (const float*)d_in[15];
    const float* whh2 = (const float*)d_in[16];
    const float* bih2 = (const float*)d_in[17];
    const float* bhh2 = (const float*)d_in[18];
    const float* Wp   = (const float*)d_in[19];
    const float* bp   = (const float*)d_in[20];
    const int* src    = (const int*)d_in[21];
    const int* dst    = (const int*)d_in[22];
    const int* ety    = (const int*)d_in[23];
    float* out = (float*)d_out;

    static int inited = 0;
    if (!inited) {
        cudaFuncSetAttribute(step_kernel,
                             cudaFuncAttributeMaxDynamicSharedMemorySize, ST_SMEM);
        cudaFuncSetAttribute(attn_kernel,
                             cudaFuncAttributeMaxDynamicSharedMemorySize, ATT_SMEM);
        inited = 1;
    }

    prep_kernel<<<192, 256>>>(W_edge, gWih, gWhh);
    prep_lstm<<<452, 256>>>(wih0, whh0, bih0, bhh0,
                            wih1, whh1, bih1, bhh1,
                            wih2, whh2, bih2, bhh2);
    sort_kernel<<<NGR, 640>>>(src, dst, ety);
    for (int s = 0; s < 5; s++)
        step_kernel<<<NGR * 2, NTH, ST_SMEM>>>(feats, b_edge, gbih, gbhh, s);
    for (int it = 0; it < 6; it++) {
        lstm_kernel<<<40, 256>>>();
        attn_kernel<<<NGR, 256, ATT_SMEM>>>(Wp, bp, out, it == 5 ? 1 : 0);
    }
}